// round 8
// baseline (speedup 1.0000x reference)
#include <cuda_runtime.h>

#define NN 50000
#define EE 800000
#define FULL 0xffffffffu

// ---------------- device scratch ----------------
__device__ float g_bufT[NN * 128];   // GEMM outputs (messages)
__device__ float g_bufX[NN * 128];   // layer activations
__device__ float g_dinv[NN];
__device__ int   g_cnt[NN];
__device__ int   g_off[NN];
__device__ int   g_cur[NN];
__device__ int   g_tot;
__device__ int   g_es[EE];           // CSR: src ids grouped by dst
__device__ float2 g_Sv[NN];          // per-node per-head <g, a_src>
__device__ float2 g_Dv[NN];          // per-node per-head <g, a_dst>
__device__ float2 g_eb[EE];          // cached per-edge raw scores (2 heads)

// ---------------- helpers ----------------
__device__ __forceinline__ float lrelu(float x) { return x > 0.f ? x : 0.2f * x; }

// ---------------- CSR build ----------------
__global__ void k_cnt_zero(int n) {
    int i = blockIdx.x * blockDim.x + threadIdx.x;
    if (i == 0) g_tot = 0;
    if (i < n) g_cnt[i] = 0;
}
__global__ void k_hist(const int* __restrict__ dst, int e) {
    int i = blockIdx.x * blockDim.x + threadIdx.x;
    if (i < e) atomicAdd(&g_cnt[dst[i]], 1);
}
__global__ void k_off(int n) {
    int i = blockIdx.x * blockDim.x + threadIdx.x;
    if (i >= n) return;
    int c = g_cnt[i];
    int p = atomicAdd(&g_tot, c);
    g_off[i] = p;
    g_cur[i] = p;
    g_dinv[i] = rsqrtf((float)(c + 1));
}
__global__ void k_fill(const int* __restrict__ src, const int* __restrict__ dst, int e) {
    int i = blockIdx.x * blockDim.x + threadIdx.x;
    if (i >= e) return;
    int d = dst[i];
    int p = atomicAdd(&g_cur[d], 1);
    g_es[p] = src[i];
}

// ---------------- register-tiled GEMM: Y[n,J] = X[n,K] @ W[K,J] ----------------
// 128 rows/block, 256 threads (16x16), each thread 8 rows x 4*(J/64) cols.
// SCALE: multiply output row by g_dinv[row] (GCN source pre-scaling).
// SD=1: emit GAT score dots for CH=64/J=128; SD=2: CH=32/J=64.
template <int K, int J, int SD, bool SCALE>
__global__ __launch_bounds__(256)
void k_gemm(const float* __restrict__ X, const float* __restrict__ W,
            float* __restrict__ Y, const float* __restrict__ asv,
            const float* __restrict__ adv, int n) {
    __shared__ float Ws[K * J];
    __shared__ float Xs[32 * 128];
    const int JT = J / 64;
    int tid = threadIdx.x;
    int tx = tid & 15, ty = tid >> 4;
    int row0 = blockIdx.x * 128;

    for (int i = tid; i < K * J / 4; i += 256)
        ((float4*)Ws)[i] = ((const float4*)W)[i];

    float acc[JT][8][4];
#pragma unroll
    for (int jc = 0; jc < JT; jc++)
#pragma unroll
        for (int i = 0; i < 8; i++)
#pragma unroll
            for (int c = 0; c < 4; c++) acc[jc][i][c] = 0.f;

    for (int k0 = 0; k0 < K; k0 += 32) {
        __syncthreads();
#pragma unroll
        for (int it = 0; it < 4; it++) {
            int i = tid + it * 256;
            int r = i >> 3, c4 = i & 7;
            int gr = row0 + r;
            float4 v = make_float4(0.f, 0.f, 0.f, 0.f);
            if (gr < n) v = ((const float4*)X)[(size_t)gr * (K / 4) + (k0 >> 2) + c4];
            int kk = c4 * 4;
            Xs[(kk + 0) * 128 + r] = v.x;
            Xs[(kk + 1) * 128 + r] = v.y;
            Xs[(kk + 2) * 128 + r] = v.z;
            Xs[(kk + 3) * 128 + r] = v.w;
        }
        __syncthreads();
#pragma unroll
        for (int kk = 0; kk < 32; kk++) {
            float xr[8];
            *(float4*)xr = *(const float4*)(Xs + kk * 128 + ty * 8);
            *(float4*)(xr + 4) = *(const float4*)(Xs + kk * 128 + ty * 8 + 4);
#pragma unroll
            for (int jc = 0; jc < JT; jc++) {
                float wr[4];
                *(float4*)wr = *(const float4*)(Ws + (k0 + kk) * J + jc * 64 + tx * 4);
#pragma unroll
                for (int i = 0; i < 8; i++)
#pragma unroll
                    for (int c = 0; c < 4; c++) acc[jc][i][c] += xr[i] * wr[c];
            }
        }
    }
#pragma unroll
    for (int i = 0; i < 8; i++) {
        int gr = row0 + ty * 8 + i;
        if (gr >= n) continue;
        float dd = SCALE ? g_dinv[gr] : 1.f;
#pragma unroll
        for (int jc = 0; jc < JT; jc++) {
            float4 v = make_float4(dd * acc[jc][i][0], dd * acc[jc][i][1],
                                   dd * acc[jc][i][2], dd * acc[jc][i][3]);
            ((float4*)Y)[(size_t)gr * (J / 4) + jc * 16 + tx] = v;
        }
    }

    if (SD == 1) {
        float as[2][4], ad[2][4];
#pragma unroll
        for (int jc = 0; jc < JT; jc++)
#pragma unroll
            for (int c = 0; c < 4; c++) {
                as[jc][c] = asv[jc * 64 + tx * 4 + c];
                ad[jc][c] = adv[jc * 64 + tx * 4 + c];
            }
#pragma unroll
        for (int i = 0; i < 8; i++) {
            float s0 = 0.f, d0 = 0.f, s1 = 0.f, d1 = 0.f;
#pragma unroll
            for (int c = 0; c < 4; c++) {
                s0 += acc[0][i][c] * as[0][c];
                d0 += acc[0][i][c] * ad[0][c];
                s1 += acc[JT - 1][i][c] * as[1][c];
                d1 += acc[JT - 1][i][c] * ad[1][c];
            }
#pragma unroll
            for (int o = 8; o; o >>= 1) {
                s0 += __shfl_xor_sync(FULL, s0, o);
                d0 += __shfl_xor_sync(FULL, d0, o);
                s1 += __shfl_xor_sync(FULL, s1, o);
                d1 += __shfl_xor_sync(FULL, d1, o);
            }
            int gr = row0 + ty * 8 + i;
            if (tx == 0 && gr < n) {
                g_Sv[gr] = make_float2(s0, s1);
                g_Dv[gr] = make_float2(d0, d1);
            }
        }
    } else if (SD == 2) {
        float as[4], ad[4];
        int h = tx >> 3;
#pragma unroll
        for (int c = 0; c < 4; c++) {
            as[c] = asv[h * 32 + (tx & 7) * 4 + c];
            ad[c] = adv[h * 32 + (tx & 7) * 4 + c];
        }
#pragma unroll
        for (int i = 0; i < 8; i++) {
            float s = 0.f, d = 0.f;
#pragma unroll
            for (int c = 0; c < 4; c++) {
                s += acc[0][i][c] * as[c];
                d += acc[0][i][c] * ad[c];
            }
#pragma unroll
            for (int o = 4; o; o >>= 1) {
                s += __shfl_xor_sync(FULL, s, o);
                d += __shfl_xor_sync(FULL, d, o);
            }
            int gr = row0 + ty * 8 + i;
            if ((tx & 7) == 0 && gr < n) {
                ((float*)g_Sv)[gr * 2 + h] = s;
                ((float*)g_Dv)[gr * 2 + h] = d;
            }
        }
    }
}

// ---------------- GCN: HALF-warp per node; T rows pre-scaled by dinv_src ----------------
// Exact grid (n*16 threads), no tails. Exact trip count in shfl loop (no padding).
__global__ void k_gcn_node(const float* __restrict__ T, const float* __restrict__ b,
                           float* __restrict__ X, int n) {
    int g = blockIdx.x * blockDim.x + threadIdx.x;
    int w = g >> 4;
    int lane = threadIdx.x & 15;
    if (w >= n) return;
    const float4* T4 = (const float4*)T;
    float4 self = T4[(size_t)w * 16 + lane];   // m_w = dinv_w * (XW)_w
    float ax = self.x, ay = self.y, az = self.z, aw = self.w;
    int beg = g_off[w], end = beg + g_cnt[w];
    for (int base = beg; base < end; base += 16) {
        int j = base + lane;
        int sj = (j < end) ? g_es[j] : w;
        int cnt = min(16, end - base);
        for (int t = 0; t < cnt; t++) {
            int s = __shfl_sync(FULL, sj, t, 16);
            float4 v = T4[(size_t)s * 16 + lane];
            ax += v.x; ay += v.y; az += v.z; aw += v.w;
        }
    }
    float dd = g_dinv[w];
    float4 bb = ((const float4*)b)[lane];
    float4 o;
    o.x = fmaxf(dd * ax + bb.x, 0.f);
    o.y = fmaxf(dd * ay + bb.y, 0.f);
    o.z = fmaxf(dd * az + bb.z, 0.f);
    o.w = fmaxf(dd * aw + bb.w, 0.f);
    ((float4*)X)[(size_t)w * 16 + lane] = o;
}

// ---------------- fused GAT layer: warp per node, online softmax + cached scores ----
template <int CH, bool CONCAT>
__global__ void k_gat_node(const float* __restrict__ T, const float* __restrict__ bias,
                           float* __restrict__ X, float* __restrict__ out, int n) {
    int w = (blockIdx.x * blockDim.x + threadIdx.x) >> 5;
    int lane = threadIdx.x & 31;
    if (w >= n) return;
    float2 Dd = g_Dv[w];
    float2 Sw = g_Sv[w];
    float self0 = lrelu(Sw.x + Dd.x);
    float self1 = lrelu(Sw.y + Dd.y);
    int beg = g_off[w], end = beg + g_cnt[w];

    // --- pass 1: online max+sum, cache raw scores sequentially ---
    float m0 = (lane == 0) ? self0 : -1e30f;
    float m1 = (lane == 0) ? self1 : -1e30f;
    float z0 = (lane == 0) ? 1.f : 0.f;
    float z1 = (lane == 0) ? 1.f : 0.f;
    for (int j = beg + lane; j < end; j += 32) {
        float2 sv = g_Sv[g_es[j]];
        float e0 = lrelu(sv.x + Dd.x);
        float e1 = lrelu(sv.y + Dd.y);
        g_eb[j] = make_float2(e0, e1);
        if (e0 > m0) { z0 = z0 * __expf(m0 - e0) + 1.f; m0 = e0; }
        else           z0 += __expf(e0 - m0);
        if (e1 > m1) { z1 = z1 * __expf(m1 - e1) + 1.f; m1 = e1; }
        else           z1 += __expf(e1 - m1);
    }
#pragma unroll
    for (int o = 16; o; o >>= 1) {
        float om = __shfl_xor_sync(FULL, m0, o);
        float oz = __shfl_xor_sync(FULL, z0, o);
        float M = fmaxf(m0, om);
        z0 = z0 * __expf(m0 - M) + oz * __expf(om - M);
        m0 = M;
        om = __shfl_xor_sync(FULL, m1, o);
        oz = __shfl_xor_sync(FULL, z1, o);
        M = fmaxf(m1, om);
        z1 = z1 * __expf(m1 - M) + oz * __expf(om - M);
        m1 = M;
    }
    float iz0 = 1.f / (z0 + 1e-16f);
    float iz1 = 1.f / (z1 + 1e-16f);

    // --- pass 2: weighted feature accumulate ---
    constexpr int VEC = (CH == 64) ? 4 : 2;
    float acc[VEC];
    float wself = (lane < 16) ? __expf(self0 - m0) * iz0 : __expf(self1 - m1) * iz1;
    if (CH == 64) {
        float4 v = ((const float4*)T)[(size_t)w * 32 + lane];
        acc[0] = wself * v.x; acc[1] = wself * v.y;
        acc[2] = wself * v.z; acc[3] = wself * v.w;
    } else {
        float2 v = ((const float2*)T)[(size_t)w * 32 + lane];
        acc[0] = wself * v.x; acc[1] = wself * v.y;
    }
    for (int base = beg; base < end; base += 32) {
        int j = base + lane;
        int sj = w; float a0 = 0.f, a1 = 0.f;
        if (j < end) {
            sj = g_es[j];
            float2 eb = g_eb[j];
            a0 = __expf(eb.x - m0) * iz0;
            a1 = __expf(eb.y - m1) * iz1;
        }
        int cnt4 = (min(32, end - base) + 3) & ~3;
        for (int t = 0; t < cnt4; t += 4) {
#pragma unroll
            for (int u = 0; u < 4; u++) {
                int s = __shfl_sync(FULL, sj, t + u);
                float wa = __shfl_sync(FULL, a0, t + u);
                float wb = __shfl_sync(FULL, a1, t + u);
                float wgt = (lane < 16) ? wa : wb;
                if (CH == 64) {
                    float4 v = ((const float4*)T)[(size_t)s * 32 + lane];
                    acc[0] += wgt * v.x; acc[1] += wgt * v.y;
                    acc[2] += wgt * v.z; acc[3] += wgt * v.w;
                } else {
                    float2 v = ((const float2*)T)[(size_t)s * 32 + lane];
                    acc[0] += wgt * v.x; acc[1] += wgt * v.y;
                }
            }
        }
    }

    if (CONCAT) {
        float4 bb = ((const float4*)bias)[lane];
        float4 o;
        o.x = fmaxf(acc[0] + bb.x, 0.f);
        o.y = fmaxf(acc[1] + bb.y, 0.f);
        o.z = fmaxf(acc[2] + bb.z, 0.f);
        o.w = fmaxf(acc[3] + bb.w, 0.f);
        ((float4*)X)[(size_t)w * 32 + lane] = o;
    } else {
        float x0 = __shfl_sync(FULL, acc[0], lane >> 1);
        float x1 = __shfl_sync(FULL, acc[1], lane >> 1);
        float h0 = (lane & 1) ? x1 : x0;
        float y0 = __shfl_sync(FULL, acc[0], 16 + (lane >> 1));
        float y1 = __shfl_sync(FULL, acc[1], 16 + (lane >> 1));
        float h1 = (lane & 1) ? y1 : y0;
        float v = 0.5f * (h0 + h1) + bias[lane];
        float mx = v;
#pragma unroll
        for (int o = 16; o; o >>= 1) mx = fmaxf(mx, __shfl_xor_sync(FULL, mx, o));
        float ex = __expf(v - mx);
        float sum = ex;
#pragma unroll
        for (int o = 16; o; o >>= 1) sum += __shfl_xor_sync(FULL, sum, o);
        out[(size_t)w * 32 + lane] = v - mx - logf(sum);
    }
}

// ---------------- launcher ----------------
static inline int cdiv(long long a, int b) { return (int)((a + b - 1) / b); }

extern "C" void kernel_launch(void* const* d_in, const int* in_sizes, int n_in,
                              void* d_out, int out_size) {
    const float* x   = (const float*)d_in[0];
    const int*   ei  = (const int*)d_in[1];
    const float* W1  = (const float*)d_in[2];
    const float* b1  = (const float*)d_in[3];
    const float* W2  = (const float*)d_in[4];
    const float* b2  = (const float*)d_in[5];
    const float* Wg1 = (const float*)d_in[6];
    const float* as1 = (const float*)d_in[7];
    const float* ad1 = (const float*)d_in[8];
    const float* bg1 = (const float*)d_in[9];
    const float* Wg2 = (const float*)d_in[10];
    const float* as2 = (const float*)d_in[11];
    const float* ad2 = (const float*)d_in[12];
    const float* bg2 = (const float*)d_in[13];

    int n = in_sizes[0] / 128;
    int e = in_sizes[1] / 2;
    const int* src = ei;
    const int* dst = ei + e;

    float* T = nullptr; cudaGetSymbolAddress((void**)&T, g_bufT);
    float* X = nullptr; cudaGetSymbolAddress((void**)&X, g_bufX);
    float* out = (float*)d_out;

    static cudaStream_t s1 = nullptr;
    static cudaEvent_t e0 = nullptr, eDinv = nullptr, eCsr = nullptr;
    if (!s1) {
        cudaStreamCreateWithFlags(&s1, cudaStreamNonBlocking);
        cudaEventCreateWithFlags(&e0, cudaEventDisableTiming);
        cudaEventCreateWithFlags(&eDinv, cudaEventDisableTiming);
        cudaEventCreateWithFlags(&eCsr, cudaEventDisableTiming);
    }

    const int B = 256;
    int half_blocks = cdiv((long long)n * 16, B);   // exact for n=50000
    int warp_blocks = cdiv((long long)n * 32, B);   // exact
    int gemm_blocks = cdiv(n, 128);

    // --- fork: CSR build on side stream ---
    cudaEventRecord(e0, 0);
    cudaStreamWaitEvent(s1, e0, 0);
    k_cnt_zero<<<cdiv(n, B), B, 0, s1>>>(n);
    k_hist<<<cdiv(e, B), B, 0, s1>>>(dst, e);
    k_off<<<cdiv(n, B), B, 0, s1>>>(n);
    cudaEventRecord(eDinv, s1);          // dinv ready (GEMM1 needs it)
    k_fill<<<cdiv(e, B), B, 0, s1>>>(src, dst, e);
    cudaEventRecord(eCsr, s1);

    // --- GCN1: 128 -> 64 (rows pre-scaled by dinv) ---
    cudaStreamWaitEvent(0, eDinv, 0);
    k_gemm<128, 64, 0, true><<<gemm_blocks, 256>>>(x, W1, T, nullptr, nullptr, n);
    cudaStreamWaitEvent(0, eCsr, 0);     // CSR lists ready before aggregation
    k_gcn_node<<<half_blocks, B>>>(T, b1, X, n);

    // --- GCN2: 64 -> 64 ---
    k_gemm<64, 64, 0, true><<<gemm_blocks, 256>>>(X, W2, T, nullptr, nullptr, n);
    k_gcn_node<<<half_blocks, B>>>(T, b2, X, n);

    // --- GAT1: 64 -> 2x64 concat (scores fused into GEMM epilogue) ---
    k_gemm<64, 128, 1, false><<<gemm_blocks, 256>>>(X, Wg1, T, as1, ad1, n);
    k_gat_node<64, true><<<warp_blocks, B>>>(T, bg1, X, nullptr, n);

    // --- GAT2: 128 -> 2x32 mean + log_softmax ---
    k_gemm<128, 64, 2, false><<<gemm_blocks, 256>>>(X, Wg2, T, as2, ad2, n);
    k_gat_node<32, false><<<warp_blocks, B>>>(T, bg2, nullptr, out, n);
}

// round 9
// speedup vs baseline: 1.0655x; 1.0655x over previous
#include <cuda_runtime.h>
#include <cuda_fp16.h>

#define NN 50000
#define EE 800000
#define FULL 0xffffffffu

// ---------------- device scratch ----------------
__device__ __align__(16) __half g_bufT[NN * 128];  // GEMM outputs (messages, fp16)
__device__ __align__(16) float  g_bufX[NN * 128];  // layer activations (fp32)
__device__ float  g_dinv[NN];
__device__ int    g_cnt[NN];
__device__ int    g_off[NN];
__device__ int    g_cur[NN];
__device__ int    g_tot;
__device__ int    g_es[EE];          // CSR: src ids grouped by dst
__device__ float2 g_Sv[NN];          // per-node per-head <g, a_src>
__device__ float2 g_Dv[NN];          // per-node per-head <g, a_dst>
__device__ float2 g_eb[EE];          // cached per-edge raw scores (2 heads)

// ---------------- helpers ----------------
__device__ __forceinline__ float lrelu(float x) { return x > 0.f ? x : 0.2f * x; }

__device__ __forceinline__ float4 h4tof4(uint2 q) {
    float2 f0 = __half22float2(*(__half2*)&q.x);
    float2 f1 = __half22float2(*(__half2*)&q.y);
    return make_float4(f0.x, f0.y, f1.x, f1.y);
}

// ---------------- CSR build ----------------
__global__ void k_cnt_zero(int n) {
    int i = blockIdx.x * blockDim.x + threadIdx.x;
    if (i == 0) g_tot = 0;
    if (i < n) g_cnt[i] = 0;
}
__global__ void k_hist(const int* __restrict__ dst, int e) {
    int i = blockIdx.x * blockDim.x + threadIdx.x;
    if (i < e) atomicAdd(&g_cnt[dst[i]], 1);
}
__global__ void k_off(int n) {
    int i = blockIdx.x * blockDim.x + threadIdx.x;
    if (i >= n) return;
    int c = g_cnt[i];
    int p = atomicAdd(&g_tot, c);
    g_off[i] = p;
    g_cur[i] = p;
    g_dinv[i] = rsqrtf((float)(c + 1));
}
__global__ void k_fill(const int* __restrict__ src, const int* __restrict__ dst, int e) {
    int i = blockIdx.x * blockDim.x + threadIdx.x;
    if (i >= e) return;
    int d = dst[i];
    int p = atomicAdd(&g_cur[d], 1);
    g_es[p] = src[i];
}

// ---------------- register-tiled GEMM: Y[n,J] = X[n,K] @ W[K,J], fp16 out ----------
// 128 rows/block, 256 threads (16x16), each thread 8 rows x 4*(J/64) cols.
// SCALE: multiply output row by g_dinv[row]. SD=1: GAT1 score dots; SD=2: GAT2.
template <int K, int J, int SD, bool SCALE>
__global__ __launch_bounds__(256)
void k_gemm(const float* __restrict__ X, const float* __restrict__ W,
            __half* __restrict__ Y, const float* __restrict__ asv,
            const float* __restrict__ adv, int n) {
    __shared__ float Ws[K * J];
    __shared__ float Xs[32 * 128];
    const int JT = J / 64;
    int tid = threadIdx.x;
    int tx = tid & 15, ty = tid >> 4;
    int row0 = blockIdx.x * 128;

    for (int i = tid; i < K * J / 4; i += 256)
        ((float4*)Ws)[i] = ((const float4*)W)[i];

    float acc[JT][8][4];
#pragma unroll
    for (int jc = 0; jc < JT; jc++)
#pragma unroll
        for (int i = 0; i < 8; i++)
#pragma unroll
            for (int c = 0; c < 4; c++) acc[jc][i][c] = 0.f;

    for (int k0 = 0; k0 < K; k0 += 32) {
        __syncthreads();
#pragma unroll
        for (int it = 0; it < 4; it++) {
            int i = tid + it * 256;
            int r = i >> 3, c4 = i & 7;
            int gr = row0 + r;
            float4 v = make_float4(0.f, 0.f, 0.f, 0.f);
            if (gr < n) v = ((const float4*)X)[(size_t)gr * (K / 4) + (k0 >> 2) + c4];
            int kk = c4 * 4;
            Xs[(kk + 0) * 128 + r] = v.x;
            Xs[(kk + 1) * 128 + r] = v.y;
            Xs[(kk + 2) * 128 + r] = v.z;
            Xs[(kk + 3) * 128 + r] = v.w;
        }
        __syncthreads();
#pragma unroll
        for (int kk = 0; kk < 32; kk++) {
            float xr[8];
            *(float4*)xr = *(const float4*)(Xs + kk * 128 + ty * 8);
            *(float4*)(xr + 4) = *(const float4*)(Xs + kk * 128 + ty * 8 + 4);
#pragma unroll
            for (int jc = 0; jc < JT; jc++) {
                float wr[4];
                *(float4*)wr = *(const float4*)(Ws + (k0 + kk) * J + jc * 64 + tx * 4);
#pragma unroll
                for (int i = 0; i < 8; i++)
#pragma unroll
                    for (int c = 0; c < 4; c++) acc[jc][i][c] += xr[i] * wr[c];
            }
        }
    }
#pragma unroll
    for (int i = 0; i < 8; i++) {
        int gr = row0 + ty * 8 + i;
        if (gr >= n) continue;
        float dd = SCALE ? g_dinv[gr] : 1.f;
#pragma unroll
        for (int jc = 0; jc < JT; jc++) {
            __half2 p0 = __floats2half2_rn(dd * acc[jc][i][0], dd * acc[jc][i][1]);
            __half2 p1 = __floats2half2_rn(dd * acc[jc][i][2], dd * acc[jc][i][3]);
            uint2 st;
            st.x = *(unsigned*)&p0;
            st.y = *(unsigned*)&p1;
            ((uint2*)Y)[(size_t)gr * (J / 4) + jc * 16 + tx] = st;
        }
    }

    if (SD == 1) {
        float as[2][4], ad[2][4];
#pragma unroll
        for (int jc = 0; jc < JT; jc++)
#pragma unroll
            for (int c = 0; c < 4; c++) {
                as[jc][c] = asv[jc * 64 + tx * 4 + c];
                ad[jc][c] = adv[jc * 64 + tx * 4 + c];
            }
#pragma unroll
        for (int i = 0; i < 8; i++) {
            float s0 = 0.f, d0 = 0.f, s1 = 0.f, d1 = 0.f;
#pragma unroll
            for (int c = 0; c < 4; c++) {
                s0 += acc[0][i][c] * as[0][c];
                d0 += acc[0][i][c] * ad[0][c];
                s1 += acc[JT - 1][i][c] * as[1][c];
                d1 += acc[JT - 1][i][c] * ad[1][c];
            }
#pragma unroll
            for (int o = 8; o; o >>= 1) {
                s0 += __shfl_xor_sync(FULL, s0, o);
                d0 += __shfl_xor_sync(FULL, d0, o);
                s1 += __shfl_xor_sync(FULL, s1, o);
                d1 += __shfl_xor_sync(FULL, d1, o);
            }
            int gr = row0 + ty * 8 + i;
            if (tx == 0 && gr < n) {
                g_Sv[gr] = make_float2(s0, s1);
                g_Dv[gr] = make_float2(d0, d1);
            }
        }
    } else if (SD == 2) {
        float as[4], ad[4];
        int h = tx >> 3;
#pragma unroll
        for (int c = 0; c < 4; c++) {
            as[c] = asv[h * 32 + (tx & 7) * 4 + c];
            ad[c] = adv[h * 32 + (tx & 7) * 4 + c];
        }
#pragma unroll
        for (int i = 0; i < 8; i++) {
            float s = 0.f, d = 0.f;
#pragma unroll
            for (int c = 0; c < 4; c++) {
                s += acc[0][i][c] * as[c];
                d += acc[0][i][c] * ad[c];
            }
#pragma unroll
            for (int o = 4; o; o >>= 1) {
                s += __shfl_xor_sync(FULL, s, o);
                d += __shfl_xor_sync(FULL, d, o);
            }
            int gr = row0 + ty * 8 + i;
            if ((tx & 7) == 0 && gr < n) {
                ((float*)g_Sv)[gr * 2 + h] = s;
                ((float*)g_Dv)[gr * 2 + h] = d;
            }
        }
    }
}

// ---------------- GCN1: 16 lanes/node, fp16 rows, per-edge dinv (R4 structure) -----
__global__ void k_gcn_node1(const __half* __restrict__ T, const float* __restrict__ b,
                            float* __restrict__ X, int n) {
    int g = blockIdx.x * blockDim.x + threadIdx.x;
    int w = g >> 4;
    int lane = threadIdx.x & 15;
    if (w >= n) return;
    const uint2* T2 = (const uint2*)T;   // row = 64 halves = 16 uint2
    float dw = g_dinv[w];
    float4 self = h4tof4(T2[(size_t)w * 16 + lane]);
    float ax = dw * self.x, ay = dw * self.y, az = dw * self.z, aw = dw * self.w;
    int beg = g_off[w], end = beg + g_cnt[w];
    for (int base = beg; base < end; base += 16) {
        int j = base + lane;
        int sj = w; float cj = 0.f;
        if (j < end) { sj = g_es[j]; cj = g_dinv[sj]; }
        int cnt = min(16, end - base);
        for (int t = 0; t < cnt; t++) {
            int s = __shfl_sync(FULL, sj, t, 16);
            float c = __shfl_sync(FULL, cj, t, 16);
            float4 v = h4tof4(T2[(size_t)s * 16 + lane]);
            ax += c * v.x; ay += c * v.y; az += c * v.z; aw += c * v.w;
        }
    }
    float4 bb = ((const float4*)b)[lane];
    float4 o;
    o.x = fmaxf(dw * ax + bb.x, 0.f);
    o.y = fmaxf(dw * ay + bb.y, 0.f);
    o.z = fmaxf(dw * az + bb.z, 0.f);
    o.w = fmaxf(dw * aw + bb.w, 0.f);
    ((float4*)X)[(size_t)w * 16 + lane] = o;
}

// ---------------- GCN2: 16 lanes/node, fp16 rows pre-scaled by dinv_src ------------
__global__ void k_gcn_node2(const __half* __restrict__ T, const float* __restrict__ b,
                            float* __restrict__ X, int n) {
    int g = blockIdx.x * blockDim.x + threadIdx.x;
    int w = g >> 4;
    int lane = threadIdx.x & 15;
    if (w >= n) return;
    const uint2* T2 = (const uint2*)T;
    float4 self = h4tof4(T2[(size_t)w * 16 + lane]);
    float ax = self.x, ay = self.y, az = self.z, aw = self.w;
    int beg = g_off[w], end = beg + g_cnt[w];
    for (int base = beg; base < end; base += 16) {
        int j = base + lane;
        int sj = (j < end) ? g_es[j] : w;
        int cnt = min(16, end - base);
        for (int t = 0; t < cnt; t++) {
            int s = __shfl_sync(FULL, sj, t, 16);
            float4 v = h4tof4(T2[(size_t)s * 16 + lane]);
            ax += v.x; ay += v.y; az += v.z; aw += v.w;
        }
    }
    float dw = g_dinv[w];
    float4 bb = ((const float4*)b)[lane];
    float4 o;
    o.x = fmaxf(dw * ax + bb.x, 0.f);
    o.y = fmaxf(dw * ay + bb.y, 0.f);
    o.z = fmaxf(dw * az + bb.z, 0.f);
    o.w = fmaxf(dw * aw + bb.w, 0.f);
    ((float4*)X)[(size_t)w * 16 + lane] = o;
}

// ---------------- fused GAT layer: warp per node, fp16 features --------------------
template <int CH, bool CONCAT>
__global__ void k_gat_node(const __half* __restrict__ T, const float* __restrict__ bias,
                           float* __restrict__ X, float* __restrict__ out, int n) {
    int w = (blockIdx.x * blockDim.x + threadIdx.x) >> 5;
    int lane = threadIdx.x & 31;
    if (w >= n) return;
    float2 Dd = g_Dv[w];
    float2 Sw = g_Sv[w];
    float self0 = lrelu(Sw.x + Dd.x);
    float self1 = lrelu(Sw.y + Dd.y);
    int beg = g_off[w], end = beg + g_cnt[w];

    // --- pass 1: online max+sum, cache raw scores sequentially ---
    float m0 = (lane == 0) ? self0 : -1e30f;
    float m1 = (lane == 0) ? self1 : -1e30f;
    float z0 = (lane == 0) ? 1.f : 0.f;
    float z1 = (lane == 0) ? 1.f : 0.f;
    for (int j = beg + lane; j < end; j += 32) {
        float2 sv = g_Sv[g_es[j]];
        float e0 = lrelu(sv.x + Dd.x);
        float e1 = lrelu(sv.y + Dd.y);
        g_eb[j] = make_float2(e0, e1);
        if (e0 > m0) { z0 = z0 * __expf(m0 - e0) + 1.f; m0 = e0; }
        else           z0 += __expf(e0 - m0);
        if (e1 > m1) { z1 = z1 * __expf(m1 - e1) + 1.f; m1 = e1; }
        else           z1 += __expf(e1 - m1);
    }
#pragma unroll
    for (int o = 16; o; o >>= 1) {
        float om = __shfl_xor_sync(FULL, m0, o);
        float oz = __shfl_xor_sync(FULL, z0, o);
        float M = fmaxf(m0, om);
        z0 = z0 * __expf(m0 - M) + oz * __expf(om - M);
        m0 = M;
        om = __shfl_xor_sync(FULL, m1, o);
        oz = __shfl_xor_sync(FULL, z1, o);
        M = fmaxf(m1, om);
        z1 = z1 * __expf(m1 - M) + oz * __expf(om - M);
        m1 = M;
    }
    float iz0 = 1.f / (z0 + 1e-16f);
    float iz1 = 1.f / (z1 + 1e-16f);

    // --- pass 2: weighted feature accumulate (fp16 rows) ---
    constexpr int VEC = (CH == 64) ? 4 : 2;
    float acc[VEC];
    float wself = (lane < 16) ? __expf(self0 - m0) * iz0 : __expf(self1 - m1) * iz1;
    if (CH == 64) {
        // row = 128 halves = 32 uint2; lane -> 4 channels
        float4 v = h4tof4(((const uint2*)T)[(size_t)w * 32 + lane]);
        acc[0] = wself * v.x; acc[1] = wself * v.y;
        acc[2] = wself * v.z; acc[3] = wself * v.w;
    } else {
        // row = 64 halves = 32 half2; lane -> 2 channels
        float2 v = __half22float2(((const __half2*)T)[(size_t)w * 32 + lane]);
        acc[0] = wself * v.x; acc[1] = wself * v.y;
    }
    for (int base = beg; base < end; base += 32) {
        int j = base + lane;
        int sj = w; float a0 = 0.f, a1 = 0.f;
        if (j < end) {
            sj = g_es[j];
            float2 eb = g_eb[j];
            a0 = __expf(eb.x - m0) * iz0;
            a1 = __expf(eb.y - m1) * iz1;
        }
        int cnt4 = (min(32, end - base) + 3) & ~3;
        for (int t = 0; t < cnt4; t += 4) {
#pragma unroll
            for (int u = 0; u < 4; u++) {
                int s = __shfl_sync(FULL, sj, t + u);
                float wa = __shfl_sync(FULL, a0, t + u);
                float wb = __shfl_sync(FULL, a1, t + u);
                float wgt = (lane < 16) ? wa : wb;
                if (CH == 64) {
                    float4 v = h4tof4(((const uint2*)T)[(size_t)s * 32 + lane]);
                    acc[0] += wgt * v.x; acc[1] += wgt * v.y;
                    acc[2] += wgt * v.z; acc[3] += wgt * v.w;
                } else {
                    float2 v = __half22float2(((const __half2*)T)[(size_t)s * 32 + lane]);
                    acc[0] += wgt * v.x; acc[1] += wgt * v.y;
                }
            }
        }
    }

    if (CONCAT) {
        float4 bb = ((const float4*)bias)[lane];
        float4 o;
        o.x = fmaxf(acc[0] + bb.x, 0.f);
        o.y = fmaxf(acc[1] + bb.y, 0.f);
        o.z = fmaxf(acc[2] + bb.z, 0.f);
        o.w = fmaxf(acc[3] + bb.w, 0.f);
        ((float4*)X)[(size_t)w * 32 + lane] = o;
    } else {
        float x0 = __shfl_sync(FULL, acc[0], lane >> 1);
        float x1 = __shfl_sync(FULL, acc[1], lane >> 1);
        float h0 = (lane & 1) ? x1 : x0;
        float y0 = __shfl_sync(FULL, acc[0], 16 + (lane >> 1));
        float y1 = __shfl_sync(FULL, acc[1], 16 + (lane >> 1));
        float h1 = (lane & 1) ? y1 : y0;
        float v = 0.5f * (h0 + h1) + bias[lane];
        float mx = v;
#pragma unroll
        for (int o = 16; o; o >>= 1) mx = fmaxf(mx, __shfl_xor_sync(FULL, mx, o));
        float ex = __expf(v - mx);
        float sum = ex;
#pragma unroll
        for (int o = 16; o; o >>= 1) sum += __shfl_xor_sync(FULL, sum, o);
        out[(size_t)w * 32 + lane] = v - mx - logf(sum);
    }
}

// ---------------- launcher ----------------
static inline int cdiv(long long a, int b) { return (int)((a + b - 1) / b); }

extern "C" void kernel_launch(void* const* d_in, const int* in_sizes, int n_in,
                              void* d_out, int out_size) {
    const float* x   = (const float*)d_in[0];
    const int*   ei  = (const int*)d_in[1];
    const float* W1  = (const float*)d_in[2];
    const float* b1  = (const float*)d_in[3];
    const float* W2  = (const float*)d_in[4];
    const float* b2  = (const float*)d_in[5];
    const float* Wg1 = (const float*)d_in[6];
    const float* as1 = (const float*)d_in[7];
    const float* ad1 = (const float*)d_in[8];
    const float* bg1 = (const float*)d_in[9];
    const float* Wg2 = (const float*)d_in[10];
    const float* as2 = (const float*)d_in[11];
    const float* ad2 = (const float*)d_in[12];
    const float* bg2 = (const float*)d_in[13];

    int n = in_sizes[0] / 128;
    int e = in_sizes[1] / 2;
    const int* src = ei;
    const int* dst = ei + e;

    __half* T = nullptr; cudaGetSymbolAddress((void**)&T, g_bufT);
    float*  X = nullptr; cudaGetSymbolAddress((void**)&X, g_bufX);
    float* out = (float*)d_out;

    static cudaStream_t s1 = nullptr;
    static cudaEvent_t e0 = nullptr, eCsr = nullptr;
    if (!s1) {
        cudaStreamCreateWithFlags(&s1, cudaStreamNonBlocking);
        cudaEventCreateWithFlags(&e0, cudaEventDisableTiming);
        cudaEventCreateWithFlags(&eCsr, cudaEventDisableTiming);
    }

    const int B = 256;
    int half_blocks = cdiv((long long)n * 16, B);   // exact for n=50000
    int warp_blocks = cdiv((long long)n * 32, B);   // exact
    int gemm_blocks = cdiv(n, 128);

    // --- fork: CSR build on side stream (fully overlapped with GEMM1) ---
    cudaEventRecord(e0, 0);
    cudaStreamWaitEvent(s1, e0, 0);
    k_cnt_zero<<<cdiv(n, B), B, 0, s1>>>(n);
    k_hist<<<cdiv(e, B), B, 0, s1>>>(dst, e);
    k_off<<<cdiv(n, B), B, 0, s1>>>(n);
    k_fill<<<cdiv(e, B), B, 0, s1>>>(src, dst, e);
    cudaEventRecord(eCsr, s1);

    // --- GCN1: 128 -> 64 (no dinv dependency; per-edge dinv in node kernel) ---
    k_gemm<128, 64, 0, false><<<gemm_blocks, 256>>>(x, W1, T, nullptr, nullptr, n);
    cudaStreamWaitEvent(0, eCsr, 0);     // CSR + dinv ready before aggregation
    k_gcn_node1<<<half_blocks, B>>>(T, b1, X, n);

    // --- GCN2: 64 -> 64 (rows pre-scaled by dinv; dinv already synced) ---
    k_gemm<64, 64, 0, true><<<gemm_blocks, 256>>>(X, W2, T, nullptr, nullptr, n);
    k_gcn_node2<<<half_blocks, B>>>(T, b2, X, n);

    // --- GAT1: 64 -> 2x64 concat (scores fused into GEMM epilogue) ---
    k_gemm<64, 128, 1, false><<<gemm_blocks, 256>>>(X, Wg1, T, as1, ad1, n);
    k_gat_node<64, true><<<warp_blocks, B>>>(T, bg1, X, nullptr, n);

    // --- GAT2: 128 -> 2x32 mean + log_softmax ---
    k_gemm<128, 64, 2, false><<<gemm_blocks, 256>>>(X, Wg2, T, as2, ad2, n);
    k_gat_node<32, false><<<warp_blocks, B>>>(T, bg2, nullptr, out, n);
}

// round 10
// speedup vs baseline: 1.2353x; 1.1594x over previous
#include <cuda_runtime.h>
#include <cuda_fp16.h>

#define NN 50000
#define EE 800000
#define FULL 0xffffffffu

// ---------------- device scratch ----------------
__device__ __align__(16) __half g_bufT[NN * 128];  // GEMM outputs (messages, fp16)
__device__ __align__(16) float  g_bufX[NN * 128];  // layer activations (fp32)
__device__ float  g_dinv[NN];
__device__ int    g_cnt[NN];
__device__ int    g_off[NN];
__device__ int    g_cur[NN];
__device__ int    g_tot;
__device__ int    g_es[EE];          // CSR: src ids grouped by dst
__device__ float2 g_Sv[NN];          // per-node per-head <g, a_src>
__device__ float2 g_Dv[NN];          // per-node per-head <g, a_dst>
__device__ float2 g_eb[EE];          // cached per-edge raw scores (2 heads)

// ---------------- helpers ----------------
__device__ __forceinline__ float lrelu(float x) { return x > 0.f ? x : 0.2f * x; }

// accumulate 8 halves (one uint4 = LDG.128) * w into acc[8] (fp32)
__device__ __forceinline__ void acc8(const uint4* __restrict__ base, size_t idx,
                                     float w, float* acc) {
    uint4 q = __ldg(base + idx);
    __half2* h = (__half2*)&q;
#pragma unroll
    for (int k = 0; k < 4; k++) {
        float2 f = __half22float2(h[k]);
        acc[2 * k]     += w * f.x;
        acc[2 * k + 1] += w * f.y;
    }
}

// ---------------- CSR build ----------------
__global__ void k_cnt_zero(int n) {
    int i = blockIdx.x * blockDim.x + threadIdx.x;
    if (i == 0) g_tot = 0;
    if (i < n) g_cnt[i] = 0;
}
__global__ void k_hist(const int* __restrict__ dst, int e) {
    int i = blockIdx.x * blockDim.x + threadIdx.x;
    if (i < e) atomicAdd(&g_cnt[dst[i]], 1);
}
__global__ void k_off(int n) {
    int i = blockIdx.x * blockDim.x + threadIdx.x;
    if (i >= n) return;
    int c = g_cnt[i];
    int p = atomicAdd(&g_tot, c);
    g_off[i] = p;
    g_cur[i] = p;
    g_dinv[i] = rsqrtf((float)(c + 1));
}
__global__ void k_fill(const int* __restrict__ src, const int* __restrict__ dst, int e) {
    int i = blockIdx.x * blockDim.x + threadIdx.x;
    if (i >= e) return;
    int d = dst[i];
    int p = atomicAdd(&g_cur[d], 1);
    g_es[p] = src[i];
}

// ---------------- register-tiled GEMM: Y[n,J] = X[n,K] @ W[K,J], fp16 out ----------
template <int K, int J, int SD, bool SCALE>
__global__ __launch_bounds__(256)
void k_gemm(const float* __restrict__ X, const float* __restrict__ W,
            __half* __restrict__ Y, const float* __restrict__ asv,
            const float* __restrict__ adv, int n) {
    __shared__ float Ws[K * J];
    __shared__ float Xs[32 * 128];
    const int JT = J / 64;
    int tid = threadIdx.x;
    int tx = tid & 15, ty = tid >> 4;
    int row0 = blockIdx.x * 128;

    for (int i = tid; i < K * J / 4; i += 256)
        ((float4*)Ws)[i] = ((const float4*)W)[i];

    float acc[JT][8][4];
#pragma unroll
    for (int jc = 0; jc < JT; jc++)
#pragma unroll
        for (int i = 0; i < 8; i++)
#pragma unroll
            for (int c = 0; c < 4; c++) acc[jc][i][c] = 0.f;

    for (int k0 = 0; k0 < K; k0 += 32) {
        __syncthreads();
#pragma unroll
        for (int it = 0; it < 4; it++) {
            int i = tid + it * 256;
            int r = i >> 3, c4 = i & 7;
            int gr = row0 + r;
            float4 v = make_float4(0.f, 0.f, 0.f, 0.f);
            if (gr < n) v = ((const float4*)X)[(size_t)gr * (K / 4) + (k0 >> 2) + c4];
            int kk = c4 * 4;
            Xs[(kk + 0) * 128 + r] = v.x;
            Xs[(kk + 1) * 128 + r] = v.y;
            Xs[(kk + 2) * 128 + r] = v.z;
            Xs[(kk + 3) * 128 + r] = v.w;
        }
        __syncthreads();
#pragma unroll
        for (int kk = 0; kk < 32; kk++) {
            float xr[8];
            *(float4*)xr = *(const float4*)(Xs + kk * 128 + ty * 8);
            *(float4*)(xr + 4) = *(const float4*)(Xs + kk * 128 + ty * 8 + 4);
#pragma unroll
            for (int jc = 0; jc < JT; jc++) {
                float wr[4];
                *(float4*)wr = *(const float4*)(Ws + (k0 + kk) * J + jc * 64 + tx * 4);
#pragma unroll
                for (int i = 0; i < 8; i++)
#pragma unroll
                    for (int c = 0; c < 4; c++) acc[jc][i][c] += xr[i] * wr[c];
            }
        }
    }
#pragma unroll
    for (int i = 0; i < 8; i++) {
        int gr = row0 + ty * 8 + i;
        if (gr >= n) continue;
        float dd = SCALE ? g_dinv[gr] : 1.f;
#pragma unroll
        for (int jc = 0; jc < JT; jc++) {
            __half2 p0 = __floats2half2_rn(dd * acc[jc][i][0], dd * acc[jc][i][1]);
            __half2 p1 = __floats2half2_rn(dd * acc[jc][i][2], dd * acc[jc][i][3]);
            uint2 st;
            st.x = *(unsigned*)&p0;
            st.y = *(unsigned*)&p1;
            ((uint2*)Y)[(size_t)gr * (J / 4) + jc * 16 + tx] = st;
        }
    }

    if (SD == 1) {
        float as[2][4], ad[2][4];
#pragma unroll
        for (int jc = 0; jc < JT; jc++)
#pragma unroll
            for (int c = 0; c < 4; c++) {
                as[jc][c] = asv[jc * 64 + tx * 4 + c];
                ad[jc][c] = adv[jc * 64 + tx * 4 + c];
            }
#pragma unroll
        for (int i = 0; i < 8; i++) {
            float s0 = 0.f, d0 = 0.f, s1 = 0.f, d1 = 0.f;
#pragma unroll
            for (int c = 0; c < 4; c++) {
                s0 += acc[0][i][c] * as[0][c];
                d0 += acc[0][i][c] * ad[0][c];
                s1 += acc[JT - 1][i][c] * as[1][c];
                d1 += acc[JT - 1][i][c] * ad[1][c];
            }
#pragma unroll
            for (int o = 8; o; o >>= 1) {
                s0 += __shfl_xor_sync(FULL, s0, o);
                d0 += __shfl_xor_sync(FULL, d0, o);
                s1 += __shfl_xor_sync(FULL, s1, o);
                d1 += __shfl_xor_sync(FULL, d1, o);
            }
            int gr = row0 + ty * 8 + i;
            if (tx == 0 && gr < n) {
                g_Sv[gr] = make_float2(s0, s1);
                g_Dv[gr] = make_float2(d0, d1);
            }
        }
    } else if (SD == 2) {
        float as[4], ad[4];
        int h = tx >> 3;
#pragma unroll
        for (int c = 0; c < 4; c++) {
            as[c] = asv[h * 32 + (tx & 7) * 4 + c];
            ad[c] = adv[h * 32 + (tx & 7) * 4 + c];
        }
#pragma unroll
        for (int i = 0; i < 8; i++) {
            float s = 0.f, d = 0.f;
#pragma unroll
            for (int c = 0; c < 4; c++) {
                s += acc[0][i][c] * as[c];
                d += acc[0][i][c] * ad[c];
            }
#pragma unroll
            for (int o = 4; o; o >>= 1) {
                s += __shfl_xor_sync(FULL, s, o);
                d += __shfl_xor_sync(FULL, d, o);
            }
            int gr = row0 + ty * 8 + i;
            if ((tx & 7) == 0 && gr < n) {
                ((float*)g_Sv)[gr * 2 + h] = s;
                ((float*)g_Dv)[gr * 2 + h] = d;
            }
        }
    }
}

// ---------------- GCN: 8 lanes/node, LDG.128 rows; block=128, exact grid -----------
// PRESCALED=false: per-edge dinv gather (layer 1). true: rows carry dinv_src.
template <bool PRESCALED>
__global__ __launch_bounds__(128)
void k_gcn_node(const __half* __restrict__ T, const float* __restrict__ b,
                float* __restrict__ X, int n) {
    int g = blockIdx.x * blockDim.x + threadIdx.x;
    int w = g >> 3;
    int lane = threadIdx.x & 7;
    unsigned gmask = 0xFFu << ((threadIdx.x & 31) & ~7);
    if (w >= n) return;   // never taken (exact grid) — safety only
    const uint4* T4 = (const uint4*)T;   // row = 64 halves = 8 uint4
    float dw = g_dinv[w];
    float acc[8];
#pragma unroll
    for (int i = 0; i < 8; i++) acc[i] = 0.f;
    acc8(T4, (size_t)w * 8 + lane, PRESCALED ? 1.f : dw, acc);   // self loop
    int beg = g_off[w], end = beg + g_cnt[w];
    for (int base = beg; base < end; base += 8) {
        int j = base + lane;
        int sj = w; float cj = 0.f;
        if (j < end) { sj = g_es[j]; cj = PRESCALED ? 1.f : g_dinv[sj]; }
        int cnt = min(8, end - base);
        for (int t = 0; t < cnt; t++) {
            int s = __shfl_sync(gmask, sj, t, 8);
            float c = __shfl_sync(gmask, cj, t, 8);
            acc8(T4, (size_t)s * 8 + lane, c, acc);
        }
    }
    float bb[8];
    *(float4*)bb = ((const float4*)b)[lane * 2];
    *(float4*)(bb + 4) = ((const float4*)b)[lane * 2 + 1];
    float4 o0, o1;
    o0.x = fmaxf(dw * acc[0] + bb[0], 0.f);
    o0.y = fmaxf(dw * acc[1] + bb[1], 0.f);
    o0.z = fmaxf(dw * acc[2] + bb[2], 0.f);
    o0.w = fmaxf(dw * acc[3] + bb[3], 0.f);
    o1.x = fmaxf(dw * acc[4] + bb[4], 0.f);
    o1.y = fmaxf(dw * acc[5] + bb[5], 0.f);
    o1.z = fmaxf(dw * acc[6] + bb[6], 0.f);
    o1.w = fmaxf(dw * acc[7] + bb[7], 0.f);
    ((float4*)X)[(size_t)w * 16 + lane * 2] = o0;
    ((float4*)X)[(size_t)w * 16 + lane * 2 + 1] = o1;
}

// ---------------- fused GAT layer: SUBW lanes/node, LDG.128 rows -------------------
// CH=64: SUBW=16 (block 256); CH=32: SUBW=8 (block 128). Exact grids, subgroup masks.
template <int CH, bool CONCAT>
__global__ void k_gat_node(const __half* __restrict__ T, const float* __restrict__ bias,
                           float* __restrict__ X, float* __restrict__ out, int n) {
    constexpr int SUBW = (CH == 64) ? 16 : 8;   // row = 2*CH halves = SUBW uint4
    int g = blockIdx.x * blockDim.x + threadIdx.x;
    int w = g / SUBW;
    int lane = threadIdx.x & (SUBW - 1);
    unsigned gmask = (SUBW == 16) ? (0xFFFFu << ((threadIdx.x & 31) & 16))
                                  : (0xFFu << ((threadIdx.x & 31) & ~7));
    if (w >= n) return;   // never taken (exact grid)
    float2 Dd = g_Dv[w];
    float2 Sw = g_Sv[w];
    float self0 = lrelu(Sw.x + Dd.x);
    float self1 = lrelu(Sw.y + Dd.y);
    int beg = g_off[w], end = beg + g_cnt[w];

    // --- pass 1: online max+sum over incoming scores, cache raw scores ---
    float m0 = (lane == 0) ? self0 : -1e30f;
    float m1 = (lane == 0) ? self1 : -1e30f;
    float z0 = (lane == 0) ? 1.f : 0.f;
    float z1 = (lane == 0) ? 1.f : 0.f;
    for (int j = beg + lane; j < end; j += SUBW) {
        float2 sv = g_Sv[g_es[j]];
        float e0 = lrelu(sv.x + Dd.x);
        float e1 = lrelu(sv.y + Dd.y);
        g_eb[j] = make_float2(e0, e1);
        if (e0 > m0) { z0 = z0 * __expf(m0 - e0) + 1.f; m0 = e0; }
        else           z0 += __expf(e0 - m0);
        if (e1 > m1) { z1 = z1 * __expf(m1 - e1) + 1.f; m1 = e1; }
        else           z1 += __expf(e1 - m1);
    }
#pragma unroll
    for (int o = SUBW / 2; o; o >>= 1) {
        float om = __shfl_xor_sync(gmask, m0, o, SUBW);
        float oz = __shfl_xor_sync(gmask, z0, o, SUBW);
        float M = fmaxf(m0, om);
        z0 = z0 * __expf(m0 - M) + oz * __expf(om - M);
        m0 = M;
        om = __shfl_xor_sync(gmask, m1, o, SUBW);
        oz = __shfl_xor_sync(gmask, z1, o, SUBW);
        M = fmaxf(m1, om);
        z1 = z1 * __expf(m1 - M) + oz * __expf(om - M);
        m1 = M;
    }
    float iz0 = 1.f / (z0 + 1e-16f);
    float iz1 = 1.f / (z1 + 1e-16f);

    // --- pass 2: weighted feature accumulate (one LDG.128 per lane per edge) ---
    const uint4* T4 = (const uint4*)T;
    int hh = (lane >= SUBW / 2);
    float acc[8];
#pragma unroll
    for (int i = 0; i < 8; i++) acc[i] = 0.f;
    float wself = hh ? __expf(self1 - m1) * iz1 : __expf(self0 - m0) * iz0;
    acc8(T4, (size_t)w * SUBW + lane, wself, acc);
    for (int base = beg; base < end; base += SUBW) {
        int j = base + lane;
        int sj = w; float a0 = 0.f, a1 = 0.f;
        if (j < end) {
            sj = g_es[j];
            float2 eb = g_eb[j];
            a0 = __expf(eb.x - m0) * iz0;
            a1 = __expf(eb.y - m1) * iz1;
        }
        int cnt = min(SUBW, end - base);
        for (int t = 0; t < cnt; t++) {
            int s = __shfl_sync(gmask, sj, t, SUBW);
            float wa = __shfl_sync(gmask, a0, t, SUBW);
            float wb = __shfl_sync(gmask, a1, t, SUBW);
            float wgt = hh ? wb : wa;
            acc8(T4, (size_t)s * SUBW + lane, wgt, acc);
        }
    }

    if (CONCAT) {
        float bb[8];
        *(float4*)bb = ((const float4*)bias)[lane * 2];
        *(float4*)(bb + 4) = ((const float4*)bias)[lane * 2 + 1];
        float4 o0, o1;
        o0.x = fmaxf(acc[0] + bb[0], 0.f);
        o0.y = fmaxf(acc[1] + bb[1], 0.f);
        o0.z = fmaxf(acc[2] + bb[2], 0.f);
        o0.w = fmaxf(acc[3] + bb[3], 0.f);
        o1.x = fmaxf(acc[4] + bb[4], 0.f);
        o1.y = fmaxf(acc[5] + bb[5], 0.f);
        o1.z = fmaxf(acc[6] + bb[6], 0.f);
        o1.w = fmaxf(acc[7] + bb[7], 0.f);
        ((float4*)X)[(size_t)w * 32 + lane * 2] = o0;
        ((float4*)X)[(size_t)w * 32 + lane * 2 + 1] = o1;
    } else {
        // SUBW=8: lanes 0-3 hold head0 ch[lane*8..+7]; lanes 4-7 head1 same channels.
        float v[8];
        int cl = lane & 3;
#pragma unroll
        for (int i = 0; i < 8; i++) {
            float oth = __shfl_sync(gmask, acc[i], cl + 4, 8);
            v[i] = 0.5f * (acc[i] + oth) + bias[cl * 8 + i];
        }
        float mx = v[0];
#pragma unroll
        for (int i = 1; i < 8; i++) mx = fmaxf(mx, v[i]);
        mx = fmaxf(mx, __shfl_xor_sync(gmask, mx, 1, 8));
        mx = fmaxf(mx, __shfl_xor_sync(gmask, mx, 2, 8));
        float sum = 0.f;
#pragma unroll
        for (int i = 0; i < 8; i++) sum += __expf(v[i] - mx);
        sum += __shfl_xor_sync(gmask, sum, 1, 8);
        sum += __shfl_xor_sync(gmask, sum, 2, 8);
        float ls = logf(sum);
        if (lane < 4) {
            float4 o0, o1;
            o0.x = v[0] - mx - ls; o0.y = v[1] - mx - ls;
            o0.z = v[2] - mx - ls; o0.w = v[3] - mx - ls;
            o1.x = v[4] - mx - ls; o1.y = v[5] - mx - ls;
            o1.z = v[6] - mx - ls; o1.w = v[7] - mx - ls;
            ((float4*)out)[(size_t)w * 8 + cl * 2] = o0;
            ((float4*)out)[(size_t)w * 8 + cl * 2 + 1] = o1;
        }
    }
}

// ---------------- launcher ----------------
static inline int cdiv(long long a, int b) { return (int)((a + b - 1) / b); }

extern "C" void kernel_launch(void* const* d_in, const int* in_sizes, int n_in,
                              void* d_out, int out_size) {
    const float* x   = (const float*)d_in[0];
    const int*   ei  = (const int*)d_in[1];
    const float* W1  = (const float*)d_in[2];
    const float* b1  = (const float*)d_in[3];
    const float* W2  = (const float*)d_in[4];
    const float* b2  = (const float*)d_in[5];
    const float* Wg1 = (const float*)d_in[6];
    const float* as1 = (const float*)d_in[7];
    const float* ad1 = (const float*)d_in[8];
    const float* bg1 = (const float*)d_in[9];
    const float* Wg2 = (const float*)d_in[10];
    const float* as2 = (const float*)d_in[11];
    const float* ad2 = (const float*)d_in[12];
    const float* bg2 = (const float*)d_in[13];

    int n = in_sizes[0] / 128;
    int e = in_sizes[1] / 2;
    const int* src = ei;
    const int* dst = ei + e;

    __half* T = nullptr; cudaGetSymbolAddress((void**)&T, g_bufT);
    float*  X = nullptr; cudaGetSymbolAddress((void**)&X, g_bufX);
    float* out = (float*)d_out;

    static cudaStream_t s1 = nullptr;
    static cudaEvent_t e0 = nullptr, eCsr = nullptr;
    if (!s1) {
        cudaStreamCreateWithFlags(&s1, cudaStreamNonBlocking);
        cudaEventCreateWithFlags(&e0, cudaEventDisableTiming);
        cudaEventCreateWithFlags(&eCsr, cudaEventDisableTiming);
    }

    const int B = 256;
    int oct_blocks  = cdiv((long long)n * 8, 128);    // 3125 exact (block=128)
    int sw16_blocks = cdiv((long long)n * 16, 256);   // 3125 exact (block=256)
    int gemm_blocks = cdiv(n, 128);

    // --- fork: CSR build on side stream (fully overlapped with GEMM1) ---
    cudaEventRecord(e0, 0);
    cudaStreamWaitEvent(s1, e0, 0);
    k_cnt_zero<<<cdiv(n, B), B, 0, s1>>>(n);
    k_hist<<<cdiv(e, B), B, 0, s1>>>(dst, e);
    k_off<<<cdiv(n, B), B, 0, s1>>>(n);
    k_fill<<<cdiv(e, B), B, 0, s1>>>(src, dst, e);
    cudaEventRecord(eCsr, s1);

    // --- GCN1: 128 -> 64 (no dinv dependency; per-edge dinv in node kernel) ---
    k_gemm<128, 64, 0, false><<<gemm_blocks, 256>>>(x, W1, T, nullptr, nullptr, n);
    cudaStreamWaitEvent(0, eCsr, 0);     // CSR + dinv ready before aggregation
    k_gcn_node<false><<<oct_blocks, 128>>>(T, b1, X, n);

    // --- GCN2: 64 -> 64 (rows pre-scaled by dinv; dinv already synced) ---
    k_gemm<64, 64, 0, true><<<gemm_blocks, 256>>>(X, W2, T, nullptr, nullptr, n);
    k_gcn_node<true><<<oct_blocks, 128>>>(T, b2, X, n);

    // --- GAT1: 64 -> 2x64 concat (scores fused into GEMM epilogue) ---
    k_gemm<64, 128, 1, false><<<gemm_blocks, 256>>>(X, Wg1, T, as1, ad1, n);
    k_gat_node<64, true><<<sw16_blocks, 256>>>(T, bg1, X, nullptr, n);

    // --- GAT2: 128 -> 2x32 mean + log_softmax ---
    k_gemm<128, 64, 2, false><<<gemm_blocks, 256>>>(X, Wg2, T, as2, ad2, n);
    k_gat_node<32, false><<<oct_blocks, 128>>>(T, bg2, nullptr, out, n);
}

// round 11
// speedup vs baseline: 1.2664x; 1.0252x over previous
#include <cuda_runtime.h>
#include <cuda_fp16.h>
#include <cuda_fp8.h>

#define NN 50000
#define EE 800000
#define FULL 0xffffffffu

// ---------------- device scratch ----------------
__device__ __align__(16) unsigned char g_bufT[NN * 128]; // messages, fp8 e4m3 (bytes)
__device__ __align__(16) float g_bufX[NN * 128];         // layer activations (fp32)
__device__ float  g_dinv[NN];
__device__ int    g_cnt[NN];
__device__ int    g_off[NN];
__device__ int    g_cur[NN];
__device__ int    g_tot;
__device__ int    g_es[EE];          // CSR: src ids grouped by dst
__device__ float2 g_Sv[NN];          // per-node per-head <g, a_src>
__device__ float2 g_Dv[NN];          // per-node per-head <g, a_dst>
__device__ float2 g_eb[EE];          // cached per-edge raw scores (2 heads)

// ---------------- helpers ----------------
__device__ __forceinline__ float lrelu(float x) { return x > 0.f ? x : 0.2f * x; }

// accumulate 16 fp8 (one uint4 = LDG.128) * w into acc[16] (fp32)
__device__ __forceinline__ void acc16(const uint4* __restrict__ base, size_t idx,
                                      float w, float* acc) {
    uint4 q = __ldg(base + idx);
    unsigned v[4] = {q.x, q.y, q.z, q.w};
#pragma unroll
    for (int k = 0; k < 4; k++) {
        __half2_raw h0 = __nv_cvt_fp8x2_to_halfraw2((__nv_fp8x2_storage_t)(v[k] & 0xFFFFu), __NV_E4M3);
        __half2_raw h1 = __nv_cvt_fp8x2_to_halfraw2((__nv_fp8x2_storage_t)(v[k] >> 16), __NV_E4M3);
        float2 f0 = __half22float2(*(__half2*)&h0);
        float2 f1 = __half22float2(*(__half2*)&h1);
        acc[4 * k + 0] += w * f0.x;
        acc[4 * k + 1] += w * f0.y;
        acc[4 * k + 2] += w * f1.x;
        acc[4 * k + 3] += w * f1.y;
    }
}

__device__ __forceinline__ unsigned pack_fp8x4(float a, float b, float c, float d) {
    unsigned short p0 = __nv_cvt_float2_to_fp8x2(make_float2(a, b), __NV_SATFINITE, __NV_E4M3);
    unsigned short p1 = __nv_cvt_float2_to_fp8x2(make_float2(c, d), __NV_SATFINITE, __NV_E4M3);
    return (unsigned)p0 | ((unsigned)p1 << 16);
}

// ---------------- CSR build ----------------
__global__ void k_cnt_zero(int n) {
    int i = blockIdx.x * blockDim.x + threadIdx.x;
    if (i == 0) g_tot = 0;
    if (i < n) g_cnt[i] = 0;
}
__global__ void k_hist(const int* __restrict__ dst, int e) {
    int i = blockIdx.x * blockDim.x + threadIdx.x;
    if (i < e) atomicAdd(&g_cnt[dst[i]], 1);
}
__global__ void k_off(int n) {
    int i = blockIdx.x * blockDim.x + threadIdx.x;
    if (i >= n) return;
    int c = g_cnt[i];
    int p = atomicAdd(&g_tot, c);
    g_off[i] = p;
    g_cur[i] = p;
    g_dinv[i] = rsqrtf((float)(c + 1));
}
__global__ void k_fill(const int* __restrict__ src, const int* __restrict__ dst, int e) {
    int i = blockIdx.x * blockDim.x + threadIdx.x;
    if (i >= e) return;
    int d = dst[i];
    int p = atomicAdd(&g_cur[d], 1);
    g_es[p] = src[i];
}

// ---------------- register-tiled GEMM: Y[n,J] = X[n,K] @ W[K,J], fp8 out ----------
template <int K, int J, int SD, bool SCALE>
__global__ __launch_bounds__(256)
void k_gemm(const float* __restrict__ X, const float* __restrict__ W,
            unsigned char* __restrict__ Y, const float* __restrict__ asv,
            const float* __restrict__ adv, int n) {
    __shared__ float Ws[K * J];
    __shared__ float Xs[32 * 128];
    const int JT = J / 64;
    int tid = threadIdx.x;
    int tx = tid & 15, ty = tid >> 4;
    int row0 = blockIdx.x * 128;

    for (int i = tid; i < K * J / 4; i += 256)
        ((float4*)Ws)[i] = ((const float4*)W)[i];

    float acc[JT][8][4];
#pragma unroll
    for (int jc = 0; jc < JT; jc++)
#pragma unroll
        for (int i = 0; i < 8; i++)
#pragma unroll
            for (int c = 0; c < 4; c++) acc[jc][i][c] = 0.f;

    for (int k0 = 0; k0 < K; k0 += 32) {
        __syncthreads();
#pragma unroll
        for (int it = 0; it < 4; it++) {
            int i = tid + it * 256;
            int r = i >> 3, c4 = i & 7;
            int gr = row0 + r;
            float4 v = make_float4(0.f, 0.f, 0.f, 0.f);
            if (gr < n) v = ((const float4*)X)[(size_t)gr * (K / 4) + (k0 >> 2) + c4];
            int kk = c4 * 4;
            Xs[(kk + 0) * 128 + r] = v.x;
            Xs[(kk + 1) * 128 + r] = v.y;
            Xs[(kk + 2) * 128 + r] = v.z;
            Xs[(kk + 3) * 128 + r] = v.w;
        }
        __syncthreads();
#pragma unroll
        for (int kk = 0; kk < 32; kk++) {
            float xr[8];
            *(float4*)xr = *(const float4*)(Xs + kk * 128 + ty * 8);
            *(float4*)(xr + 4) = *(const float4*)(Xs + kk * 128 + ty * 8 + 4);
#pragma unroll
            for (int jc = 0; jc < JT; jc++) {
                float wr[4];
                *(float4*)wr = *(const float4*)(Ws + (k0 + kk) * J + jc * 64 + tx * 4);
#pragma unroll
                for (int i = 0; i < 8; i++)
#pragma unroll
                    for (int c = 0; c < 4; c++) acc[jc][i][c] += xr[i] * wr[c];
            }
        }
    }
#pragma unroll
    for (int i = 0; i < 8; i++) {
        int gr = row0 + ty * 8 + i;
        if (gr >= n) continue;
        float dd = SCALE ? g_dinv[gr] : 1.f;
#pragma unroll
        for (int jc = 0; jc < JT; jc++) {
            unsigned st = pack_fp8x4(dd * acc[jc][i][0], dd * acc[jc][i][1],
                                     dd * acc[jc][i][2], dd * acc[jc][i][3]);
            ((unsigned*)Y)[(size_t)gr * (J / 4) + jc * 16 + tx] = st;
        }
    }

    if (SD == 1) {
        float as[2][4], ad[2][4];
#pragma unroll
        for (int jc = 0; jc < JT; jc++)
#pragma unroll
            for (int c = 0; c < 4; c++) {
                as[jc][c] = asv[jc * 64 + tx * 4 + c];
                ad[jc][c] = adv[jc * 64 + tx * 4 + c];
            }
#pragma unroll
        for (int i = 0; i < 8; i++) {
            float s0 = 0.f, d0 = 0.f, s1 = 0.f, d1 = 0.f;
#pragma unroll
            for (int c = 0; c < 4; c++) {
                s0 += acc[0][i][c] * as[0][c];
                d0 += acc[0][i][c] * ad[0][c];
                s1 += acc[JT - 1][i][c] * as[1][c];
                d1 += acc[JT - 1][i][c] * ad[1][c];
            }
#pragma unroll
            for (int o = 8; o; o >>= 1) {
                s0 += __shfl_xor_sync(FULL, s0, o);
                d0 += __shfl_xor_sync(FULL, d0, o);
                s1 += __shfl_xor_sync(FULL, s1, o);
                d1 += __shfl_xor_sync(FULL, d1, o);
            }
            int gr = row0 + ty * 8 + i;
            if (tx == 0 && gr < n) {
                g_Sv[gr] = make_float2(s0, s1);
                g_Dv[gr] = make_float2(d0, d1);
            }
        }
    } else if (SD == 2) {
        float as[4], ad[4];
        int h = tx >> 3;
#pragma unroll
        for (int c = 0; c < 4; c++) {
            as[c] = asv[h * 32 + (tx & 7) * 4 + c];
            ad[c] = adv[h * 32 + (tx & 7) * 4 + c];
        }
#pragma unroll
        for (int i = 0; i < 8; i++) {
            float s = 0.f, d = 0.f;
#pragma unroll
            for (int c = 0; c < 4; c++) {
                s += acc[0][i][c] * as[c];
                d += acc[0][i][c] * ad[c];
            }
#pragma unroll
            for (int o = 4; o; o >>= 1) {
                s += __shfl_xor_sync(FULL, s, o);
                d += __shfl_xor_sync(FULL, d, o);
            }
            int gr = row0 + ty * 8 + i;
            if ((tx & 7) == 0 && gr < n) {
                ((float*)g_Sv)[gr * 2 + h] = s;
                ((float*)g_Dv)[gr * 2 + h] = d;
            }
        }
    }
}

// ---------------- GCN: 4 lanes/node, fp8 rows (1 LDG.128 per lane per edge) --------
// block=160 -> 40 nodes/block, grid = n/40 (exact for n=50000).
template <bool PRESCALED>
__global__ __launch_bounds__(160)
void k_gcn_node(const unsigned char* __restrict__ T, const float* __restrict__ b,
                float* __restrict__ X, int n) {
    int g = blockIdx.x * blockDim.x + threadIdx.x;
    int w = g >> 2;
    int lane = threadIdx.x & 3;
    unsigned gmask = 0xFu << ((threadIdx.x & 31) & ~3);
    if (w >= n) return;   // subgroup exits together; mask stays valid
    const uint4* T4 = (const uint4*)T;   // row = 64 fp8 = 4 uint4
    float dw = g_dinv[w];
    float acc[16];
#pragma unroll
    for (int i = 0; i < 16; i++) acc[i] = 0.f;
    acc16(T4, (size_t)w * 4 + lane, PRESCALED ? 1.f : dw, acc);   // self loop
    int beg = g_off[w], end = beg + g_cnt[w];
    for (int base = beg; base < end; base += 4) {
        int j = base + lane;
        int sj = w; float cj = 0.f;
        if (j < end) { sj = g_es[j]; cj = PRESCALED ? 1.f : g_dinv[sj]; }
        int cnt = min(4, end - base);
        for (int t = 0; t < cnt; t++) {
            int s = __shfl_sync(gmask, sj, t, 4);
            float c = PRESCALED ? 1.f : __shfl_sync(gmask, cj, t, 4);
            acc16(T4, (size_t)s * 4 + lane, c, acc);
        }
    }
#pragma unroll
    for (int k = 0; k < 4; k++) {
        float4 bb = ((const float4*)b)[lane * 4 + k];
        float4 o;
        o.x = fmaxf(dw * acc[4 * k + 0] + bb.x, 0.f);
        o.y = fmaxf(dw * acc[4 * k + 1] + bb.y, 0.f);
        o.z = fmaxf(dw * acc[4 * k + 2] + bb.z, 0.f);
        o.w = fmaxf(dw * acc[4 * k + 3] + bb.w, 0.f);
        ((float4*)X)[(size_t)w * 16 + lane * 4 + k] = o;
    }
}

// ---------------- fused GAT layer: SUBW lanes/node, fp8 rows -----------------------
// CH=64: SUBW=8 (block 128); CH=32: SUBW=4 (block 160). 16 channels per lane.
template <int CH, bool CONCAT>
__global__ void k_gat_node(const unsigned char* __restrict__ T,
                           const float* __restrict__ bias,
                           float* __restrict__ X, float* __restrict__ out, int n) {
    constexpr int SUBW = (CH == 64) ? 8 : 4;   // row = 2*CH fp8 = SUBW uint4
    int g = blockIdx.x * blockDim.x + threadIdx.x;
    int w = g / SUBW;
    int lane = threadIdx.x & (SUBW - 1);
    unsigned gmask = (SUBW == 8) ? (0xFFu << ((threadIdx.x & 31) & ~7))
                                 : (0xFu << ((threadIdx.x & 31) & ~3));
    if (w >= n) return;   // subgroup exits together
    float2 Dd = g_Dv[w];
    float2 Sw = g_Sv[w];
    float self0 = lrelu(Sw.x + Dd.x);
    float self1 = lrelu(Sw.y + Dd.y);
    int beg = g_off[w], end = beg + g_cnt[w];

    // --- pass 1: online max+sum over incoming scores, cache raw scores ---
    float m0 = (lane == 0) ? self0 : -1e30f;
    float m1 = (lane == 0) ? self1 : -1e30f;
    float z0 = (lane == 0) ? 1.f : 0.f;
    float z1 = (lane == 0) ? 1.f : 0.f;
    for (int j = beg + lane; j < end; j += SUBW) {
        float2 sv = g_Sv[g_es[j]];
        float e0 = lrelu(sv.x + Dd.x);
        float e1 = lrelu(sv.y + Dd.y);
        g_eb[j] = make_float2(e0, e1);
        if (e0 > m0) { z0 = z0 * __expf(m0 - e0) + 1.f; m0 = e0; }
        else           z0 += __expf(e0 - m0);
        if (e1 > m1) { z1 = z1 * __expf(m1 - e1) + 1.f; m1 = e1; }
        else           z1 += __expf(e1 - m1);
    }
#pragma unroll
    for (int o = SUBW / 2; o; o >>= 1) {
        float om = __shfl_xor_sync(gmask, m0, o, SUBW);
        float oz = __shfl_xor_sync(gmask, z0, o, SUBW);
        float M = fmaxf(m0, om);
        z0 = z0 * __expf(m0 - M) + oz * __expf(om - M);
        m0 = M;
        om = __shfl_xor_sync(gmask, m1, o, SUBW);
        oz = __shfl_xor_sync(gmask, z1, o, SUBW);
        M = fmaxf(m1, om);
        z1 = z1 * __expf(m1 - M) + oz * __expf(om - M);
        m1 = M;
    }
    float iz0 = 1.f / (z0 + 1e-16f);
    float iz1 = 1.f / (z1 + 1e-16f);

    // --- pass 2: weighted feature accumulate (one LDG.128 per lane per edge) ---
    const uint4* T4 = (const uint4*)T;
    int hh = (lane >= SUBW / 2);
    float acc[16];
#pragma unroll
    for (int i = 0; i < 16; i++) acc[i] = 0.f;
    float wself = hh ? __expf(self1 - m1) * iz1 : __expf(self0 - m0) * iz0;
    acc16(T4, (size_t)w * SUBW + lane, wself, acc);
    for (int base = beg; base < end; base += SUBW) {
        int j = base + lane;
        int sj = w; float a0 = 0.f, a1 = 0.f;
        if (j < end) {
            sj = g_es[j];
            float2 eb = g_eb[j];
            a0 = __expf(eb.x - m0) * iz0;
            a1 = __expf(eb.y - m1) * iz1;
        }
        int cnt = min(SUBW, end - base);
        for (int t = 0; t < cnt; t++) {
            int s = __shfl_sync(gmask, sj, t, SUBW);
            float wa = __shfl_sync(gmask, a0, t, SUBW);
            float wb = __shfl_sync(gmask, a1, t, SUBW);
            float wgt = hh ? wb : wa;
            acc16(T4, (size_t)s * SUBW + lane, wgt, acc);
        }
    }

    if (CONCAT) {
        // lane holds channels [lane*16, +16) of 128; bias + relu + store fp32
#pragma unroll
        for (int k = 0; k < 4; k++) {
            float4 bb = ((const float4*)bias)[lane * 4 + k];
            float4 o;
            o.x = fmaxf(acc[4 * k + 0] + bb.x, 0.f);
            o.y = fmaxf(acc[4 * k + 1] + bb.y, 0.f);
            o.z = fmaxf(acc[4 * k + 2] + bb.z, 0.f);
            o.w = fmaxf(acc[4 * k + 3] + bb.w, 0.f);
            ((float4*)X)[(size_t)w * 32 + lane * 4 + k] = o;
        }
    } else {
        // SUBW=4: lanes 0,1 = head0 ch[lane*16..+15]; lanes 2,3 = head1 same ch.
        float v[16];
        int cl = lane & 1;
#pragma unroll
        for (int i = 0; i < 16; i++) {
            float oth = __shfl_sync(gmask, acc[i], (threadIdx.x & 2) ? (cl) : (cl + 2), 4);
            // partner lane = lane ^ 2 within subgroup
            v[i] = 0.5f * (acc[i] + oth) + bias[cl * 16 + i];
        }
        float mx = v[0];
#pragma unroll
        for (int i = 1; i < 16; i++) mx = fmaxf(mx, v[i]);
        mx = fmaxf(mx, __shfl_xor_sync(gmask, mx, 1, 4));
        float sum = 0.f;
#pragma unroll
        for (int i = 0; i < 16; i++) sum += __expf(v[i] - mx);
        sum += __shfl_xor_sync(gmask, sum, 1, 4);
        float ls = logf(sum);
        if (lane < 2) {
#pragma unroll
            for (int k = 0; k < 4; k++) {
                float4 o;
                o.x = v[4 * k + 0] - mx - ls;
                o.y = v[4 * k + 1] - mx - ls;
                o.z = v[4 * k + 2] - mx - ls;
                o.w = v[4 * k + 3] - mx - ls;
                ((float4*)out)[(size_t)w * 8 + cl * 4 + k] = o;
            }
        }
    }
}

// ---------------- launcher ----------------
static inline int cdiv(long long a, int b) { return (int)((a + b - 1) / b); }

extern "C" void kernel_launch(void* const* d_in, const int* in_sizes, int n_in,
                              void* d_out, int out_size) {
    const float* x   = (const float*)d_in[0];
    const int*   ei  = (const int*)d_in[1];
    const float* W1  = (const float*)d_in[2];
    const float* b1  = (const float*)d_in[3];
    const float* W2  = (const float*)d_in[4];
    const float* b2  = (const float*)d_in[5];
    const float* Wg1 = (const float*)d_in[6];
    const float* as1 = (const float*)d_in[7];
    const float* ad1 = (const float*)d_in[8];
    const float* bg1 = (const float*)d_in[9];
    const float* Wg2 = (const float*)d_in[10];
    const float* as2 = (const float*)d_in[11];
    const float* ad2 = (const float*)d_in[12];
    const float* bg2 = (const float*)d_in[13];

    int n = in_sizes[0] / 128;
    int e = in_sizes[1] / 2;
    const int* src = ei;
    const int* dst = ei + e;

    unsigned char* T = nullptr; cudaGetSymbolAddress((void**)&T, g_bufT);
    float* X = nullptr; cudaGetSymbolAddress((void**)&X, g_bufX);
    float* out = (float*)d_out;

    static cudaStream_t s1 = nullptr;
    static cudaEvent_t e0 = nullptr, eCsr = nullptr;
    if (!s1) {
        cudaStreamCreateWithFlags(&s1, cudaStreamNonBlocking);
        cudaEventCreateWithFlags(&e0, cudaEventDisableTiming);
        cudaEventCreateWithFlags(&eCsr, cudaEventDisableTiming);
    }

    const int B = 256;
    int quad_blocks = cdiv((long long)n * 4, 160);    // 1250 exact (block=160)
    int oct_blocks  = cdiv((long long)n * 8, 128);    // 3125 exact (block=128)
    int gemm_blocks = cdiv(n, 128);

    // --- fork: CSR build on side stream (fully overlapped with GEMM1) ---
    cudaEventRecord(e0, 0);
    cudaStreamWaitEvent(s1, e0, 0);
    k_cnt_zero<<<cdiv(n, B), B, 0, s1>>>(n);
    k_hist<<<cdiv(e, B), B, 0, s1>>>(dst, e);
    k_off<<<cdiv(n, B), B, 0, s1>>>(n);
    k_fill<<<cdiv(e, B), B, 0, s1>>>(src, dst, e);
    cudaEventRecord(eCsr, s1);

    // --- GCN1: 128 -> 64 (no dinv dependency; per-edge dinv in node kernel) ---
    k_gemm<128, 64, 0, false><<<gemm_blocks, 256>>>(x, W1, T, nullptr, nullptr, n);
    cudaStreamWaitEvent(0, eCsr, 0);     // CSR + dinv ready before aggregation
    k_gcn_node<false><<<quad_blocks, 160>>>(T, b1, X, n);

    // --- GCN2: 64 -> 64 (rows pre-scaled by dinv; dinv already synced) ---
    k_gemm<64, 64, 0, true><<<gemm_blocks, 256>>>(X, W2, T, nullptr, nullptr, n);
    k_gcn_node<true><<<quad_blocks, 160>>>(T, b2, X, n);

    // --- GAT1: 64 -> 2x64 concat (scores fused into GEMM epilogue) ---
    k_gemm<64, 128, 1, false><<<gemm_blocks, 256>>>(X, Wg1, T, as1, ad1, n);
    k_gat_node<64, true><<<oct_blocks, 128>>>(T, bg1, X, nullptr, n);

    // --- GAT2: 128 -> 2x32 mean + log_softmax ---
    k_gemm<128, 64, 2, false><<<gemm_blocks, 256>>>(X, Wg2, T, as2, ad2, n);
    k_gat_node<32, false><<<quad_blocks, 160>>>(T, bg2, nullptr, out, n);
}

// round 12
// speedup vs baseline: 1.2875x; 1.0167x over previous
#include <cuda_runtime.h>
#include <cuda_fp16.h>
#include <cuda_fp8.h>

#define NN 50000
#define EE 800000
#define FULL 0xffffffffu

// ---------------- device scratch ----------------
__device__ __align__(16) unsigned char g_bufT[NN * 128]; // messages, fp8 e4m3 (bytes)
__device__ __align__(16) float g_bufX[NN * 128];         // layer activations (fp32)
__device__ float  g_dinv[NN];
__device__ int    g_cnt[NN];
__device__ int    g_off[NN];
__device__ int    g_cur[NN];
__device__ int    g_tot;
__device__ int    g_es[EE];          // CSR: src ids grouped by dst
__device__ float2 g_Sv[NN];          // per-node per-head <g, a_src>
__device__ float2 g_Dv[NN];          // per-node per-head <g, a_dst>
__device__ float2 g_eb[EE];          // cached per-edge raw scores (2 heads)

// ---------------- helpers ----------------
__device__ __forceinline__ float lrelu(float x) { return x > 0.f ? x : 0.2f * x; }

// packed f32x2 FMA: d = a*b + d (bit-exact 2x FFMA, Blackwell FFMA2)
__device__ __forceinline__ void ffma2(unsigned long long& d, unsigned long long a,
                                      unsigned long long b) {
    asm("fma.rn.f32x2 %0, %1, %2, %0;" : "+l"(d) : "l"(a), "l"(b));
}
__device__ __forceinline__ unsigned long long pack_dup(float x) {
    unsigned long long r;
    asm("mov.b64 %0, {%1, %1};" : "=l"(r) : "r"(__float_as_uint(x)));
    return r;
}
__device__ __forceinline__ void unpack2(unsigned long long v, float& lo, float& hi) {
    unsigned a, b;
    asm("mov.b64 {%0, %1}, %2;" : "=r"(a), "=r"(b) : "l"(v));
    lo = __uint_as_float(a);
    hi = __uint_as_float(b);
}

// accumulate 16 fp8 (one uint4 = LDG.128) * w into acc[16] (fp32)
__device__ __forceinline__ void acc16(const uint4* __restrict__ base, size_t idx,
                                      float w, float* acc) {
    uint4 q = __ldg(base + idx);
    unsigned v[4] = {q.x, q.y, q.z, q.w};
#pragma unroll
    for (int k = 0; k < 4; k++) {
        __half2_raw h0 = __nv_cvt_fp8x2_to_halfraw2((__nv_fp8x2_storage_t)(v[k] & 0xFFFFu), __NV_E4M3);
        __half2_raw h1 = __nv_cvt_fp8x2_to_halfraw2((__nv_fp8x2_storage_t)(v[k] >> 16), __NV_E4M3);
        float2 f0 = __half22float2(*(__half2*)&h0);
        float2 f1 = __half22float2(*(__half2*)&h1);
        acc[4 * k + 0] += w * f0.x;
        acc[4 * k + 1] += w * f0.y;
        acc[4 * k + 2] += w * f1.x;
        acc[4 * k + 3] += w * f1.y;
    }
}

__device__ __forceinline__ unsigned pack_fp8x4(float a, float b, float c, float d) {
    unsigned short p0 = __nv_cvt_float2_to_fp8x2(make_float2(a, b), __NV_SATFINITE, __NV_E4M3);
    unsigned short p1 = __nv_cvt_float2_to_fp8x2(make_float2(c, d), __NV_SATFINITE, __NV_E4M3);
    return (unsigned)p0 | ((unsigned)p1 << 16);
}

// ---------------- CSR build ----------------
__global__ void k_cnt_zero(int n) {
    int i = blockIdx.x * blockDim.x + threadIdx.x;
    if (i == 0) g_tot = 0;
    if (i < n) g_cnt[i] = 0;
}
__global__ void k_hist(const int* __restrict__ dst, int e) {
    int i = blockIdx.x * blockDim.x + threadIdx.x;
    if (i < e) atomicAdd(&g_cnt[dst[i]], 1);
}
__global__ void k_off(int n) {
    int i = blockIdx.x * blockDim.x + threadIdx.x;
    if (i >= n) return;
    int c = g_cnt[i];
    int p = atomicAdd(&g_tot, c);
    g_off[i] = p;
    g_cur[i] = p;
    g_dinv[i] = rsqrtf((float)(c + 1));
}
__global__ void k_fill(const int* __restrict__ src, const int* __restrict__ dst, int e) {
    int i = blockIdx.x * blockDim.x + threadIdx.x;
    if (i >= e) return;
    int d = dst[i];
    int p = atomicAdd(&g_cur[d], 1);
    g_es[p] = src[i];
}

// ---------------- register-tiled GEMM (FFMA2 inner loop): Y = X @ W, fp8 out -------
template <int K, int J, int SD, bool SCALE>
__global__ __launch_bounds__(256)
void k_gemm(const float* __restrict__ X, const float* __restrict__ W,
            unsigned char* __restrict__ Y, const float* __restrict__ asv,
            const float* __restrict__ adv, int n) {
    __shared__ float Ws[K * J];
    __shared__ float Xs[32 * 128];
    const int JT = J / 64;
    int tid = threadIdx.x;
    int tx = tid & 15, ty = tid >> 4;
    int row0 = blockIdx.x * 128;

    for (int i = tid; i < K * J / 4; i += 256)
        ((float4*)Ws)[i] = ((const float4*)W)[i];

    // packed accumulators: acc2[jc][i][p] holds channels (4*... p*2, p*2+1)
    unsigned long long acc2[JT][8][2];
#pragma unroll
    for (int jc = 0; jc < JT; jc++)
#pragma unroll
        for (int i = 0; i < 8; i++) {
            acc2[jc][i][0] = 0ull;
            acc2[jc][i][1] = 0ull;
        }

    for (int k0 = 0; k0 < K; k0 += 32) {
        __syncthreads();
#pragma unroll
        for (int it = 0; it < 4; it++) {
            int i = tid + it * 256;
            int r = i >> 3, c4 = i & 7;
            int gr = row0 + r;
            float4 v = make_float4(0.f, 0.f, 0.f, 0.f);
            if (gr < n) v = ((const float4*)X)[(size_t)gr * (K / 4) + (k0 >> 2) + c4];
            int kk = c4 * 4;
            Xs[(kk + 0) * 128 + r] = v.x;
            Xs[(kk + 1) * 128 + r] = v.y;
            Xs[(kk + 2) * 128 + r] = v.z;
            Xs[(kk + 3) * 128 + r] = v.w;
        }
        __syncthreads();
#pragma unroll
        for (int kk = 0; kk < 32; kk++) {
            float xr[8];
            *(float4*)xr = *(const float4*)(Xs + kk * 128 + ty * 8);
            *(float4*)(xr + 4) = *(const float4*)(Xs + kk * 128 + ty * 8 + 4);
            unsigned long long xp[8];
#pragma unroll
            for (int i = 0; i < 8; i++) xp[i] = pack_dup(xr[i]);
#pragma unroll
            for (int jc = 0; jc < JT; jc++) {
                ulonglong2 w = *(const ulonglong2*)(Ws + (k0 + kk) * J + jc * 64 + tx * 4);
#pragma unroll
                for (int i = 0; i < 8; i++) {
                    ffma2(acc2[jc][i][0], xp[i], w.x);
                    ffma2(acc2[jc][i][1], xp[i], w.y);
                }
            }
        }
    }

    // unpack to scalar accumulators; epilogues unchanged
    float acc[JT][8][4];
#pragma unroll
    for (int jc = 0; jc < JT; jc++)
#pragma unroll
        for (int i = 0; i < 8; i++) {
            unpack2(acc2[jc][i][0], acc[jc][i][0], acc[jc][i][1]);
            unpack2(acc2[jc][i][1], acc[jc][i][2], acc[jc][i][3]);
        }

#pragma unroll
    for (int i = 0; i < 8; i++) {
        int gr = row0 + ty * 8 + i;
        if (gr >= n) continue;
        float dd = SCALE ? g_dinv[gr] : 1.f;
#pragma unroll
        for (int jc = 0; jc < JT; jc++) {
            unsigned st = pack_fp8x4(dd * acc[jc][i][0], dd * acc[jc][i][1],
                                     dd * acc[jc][i][2], dd * acc[jc][i][3]);
            ((unsigned*)Y)[(size_t)gr * (J / 4) + jc * 16 + tx] = st;
        }
    }

    if (SD == 1) {
        float as[2][4], ad[2][4];
#pragma unroll
        for (int jc = 0; jc < JT; jc++)
#pragma unroll
            for (int c = 0; c < 4; c++) {
                as[jc][c] = asv[jc * 64 + tx * 4 + c];
                ad[jc][c] = adv[jc * 64 + tx * 4 + c];
            }
#pragma unroll
        for (int i = 0; i < 8; i++) {
            float s0 = 0.f, d0 = 0.f, s1 = 0.f, d1 = 0.f;
#pragma unroll
            for (int c = 0; c < 4; c++) {
                s0 += acc[0][i][c] * as[0][c];
                d0 += acc[0][i][c] * ad[0][c];
                s1 += acc[JT - 1][i][c] * as[1][c];
                d1 += acc[JT - 1][i][c] * ad[1][c];
            }
#pragma unroll
            for (int o = 8; o; o >>= 1) {
                s0 += __shfl_xor_sync(FULL, s0, o);
                d0 += __shfl_xor_sync(FULL, d0, o);
                s1 += __shfl_xor_sync(FULL, s1, o);
                d1 += __shfl_xor_sync(FULL, d1, o);
            }
            int gr = row0 + ty * 8 + i;
            if (tx == 0 && gr < n) {
                g_Sv[gr] = make_float2(s0, s1);
                g_Dv[gr] = make_float2(d0, d1);
            }
        }
    } else if (SD == 2) {
        float as[4], ad[4];
        int h = tx >> 3;
#pragma unroll
        for (int c = 0; c < 4; c++) {
            as[c] = asv[h * 32 + (tx & 7) * 4 + c];
            ad[c] = adv[h * 32 + (tx & 7) * 4 + c];
        }
#pragma unroll
        for (int i = 0; i < 8; i++) {
            float s = 0.f, d = 0.f;
#pragma unroll
            for (int c = 0; c < 4; c++) {
                s += acc[0][i][c] * as[c];
                d += acc[0][i][c] * ad[c];
            }
#pragma unroll
            for (int o = 4; o; o >>= 1) {
                s += __shfl_xor_sync(FULL, s, o);
                d += __shfl_xor_sync(FULL, d, o);
            }
            int gr = row0 + ty * 8 + i;
            if ((tx & 7) == 0 && gr < n) {
                ((float*)g_Sv)[gr * 2 + h] = s;
                ((float*)g_Dv)[gr * 2 + h] = d;
            }
        }
    }
}

// ---------------- GCN: 4 lanes/node, fp8 rows (1 LDG.128 per lane per edge) --------
template <bool PRESCALED>
__global__ __launch_bounds__(160)
void k_gcn_node(const unsigned char* __restrict__ T, const float* __restrict__ b,
                float* __restrict__ X, int n) {
    int g = blockIdx.x * blockDim.x + threadIdx.x;
    int w = g >> 2;
    int lane = threadIdx.x & 3;
    unsigned gmask = 0xFu << ((threadIdx.x & 31) & ~3);
    if (w >= n) return;   // subgroup exits together; mask stays valid
    const uint4* T4 = (const uint4*)T;   // row = 64 fp8 = 4 uint4
    float dw = g_dinv[w];
    float acc[16];
#pragma unroll
    for (int i = 0; i < 16; i++) acc[i] = 0.f;
    acc16(T4, (size_t)w * 4 + lane, PRESCALED ? 1.f : dw, acc);   // self loop
    int beg = g_off[w], end = beg + g_cnt[w];
    for (int base = beg; base < end; base += 4) {
        int j = base + lane;
        int sj = w; float cj = 0.f;
        if (j < end) { sj = g_es[j]; cj = PRESCALED ? 1.f : g_dinv[sj]; }
        int cnt = min(4, end - base);
        for (int t = 0; t < cnt; t++) {
            int s = __shfl_sync(gmask, sj, t, 4);
            float c = PRESCALED ? 1.f : __shfl_sync(gmask, cj, t, 4);
            acc16(T4, (size_t)s * 4 + lane, c, acc);
        }
    }
#pragma unroll
    for (int k = 0; k < 4; k++) {
        float4 bb = ((const float4*)b)[lane * 4 + k];
        float4 o;
        o.x = fmaxf(dw * acc[4 * k + 0] + bb.x, 0.f);
        o.y = fmaxf(dw * acc[4 * k + 1] + bb.y, 0.f);
        o.z = fmaxf(dw * acc[4 * k + 2] + bb.z, 0.f);
        o.w = fmaxf(dw * acc[4 * k + 3] + bb.w, 0.f);
        ((float4*)X)[(size_t)w * 16 + lane * 4 + k] = o;
    }
}

// ---------------- fused GAT layer: SUBW lanes/node, fp8 rows -----------------------
template <int CH, bool CONCAT>
__global__ void k_gat_node(const unsigned char* __restrict__ T,
                           const float* __restrict__ bias,
                           float* __restrict__ X, float* __restrict__ out, int n) {
    constexpr int SUBW = (CH == 64) ? 8 : 4;   // row = 2*CH fp8 = SUBW uint4
    int g = blockIdx.x * blockDim.x + threadIdx.x;
    int w = g / SUBW;
    int lane = threadIdx.x & (SUBW - 1);
    unsigned gmask = (SUBW == 8) ? (0xFFu << ((threadIdx.x & 31) & ~7))
                                 : (0xFu << ((threadIdx.x & 31) & ~3));
    if (w >= n) return;   // subgroup exits together
    float2 Dd = g_Dv[w];
    float2 Sw = g_Sv[w];
    float self0 = lrelu(Sw.x + Dd.x);
    float self1 = lrelu(Sw.y + Dd.y);
    int beg = g_off[w], end = beg + g_cnt[w];

    // --- pass 1: online max+sum over incoming scores, cache raw scores ---
    float m0 = (lane == 0) ? self0 : -1e30f;
    float m1 = (lane == 0) ? self1 : -1e30f;
    float z0 = (lane == 0) ? 1.f : 0.f;
    float z1 = (lane == 0) ? 1.f : 0.f;
    for (int j = beg + lane; j < end; j += SUBW) {
        float2 sv = g_Sv[g_es[j]];
        float e0 = lrelu(sv.x + Dd.x);
        float e1 = lrelu(sv.y + Dd.y);
        g_eb[j] = make_float2(e0, e1);
        if (e0 > m0) { z0 = z0 * __expf(m0 - e0) + 1.f; m0 = e0; }
        else           z0 += __expf(e0 - m0);
        if (e1 > m1) { z1 = z1 * __expf(m1 - e1) + 1.f; m1 = e1; }
        else           z1 += __expf(e1 - m1);
    }
#pragma unroll
    for (int o = SUBW / 2; o; o >>= 1) {
        float om = __shfl_xor_sync(gmask, m0, o, SUBW);
        float oz = __shfl_xor_sync(gmask, z0, o, SUBW);
        float M = fmaxf(m0, om);
        z0 = z0 * __expf(m0 - M) + oz * __expf(om - M);
        m0 = M;
        om = __shfl_xor_sync(gmask, m1, o, SUBW);
        oz = __shfl_xor_sync(gmask, z1, o, SUBW);
        M = fmaxf(m1, om);
        z1 = z1 * __expf(m1 - M) + oz * __expf(om - M);
        m1 = M;
    }
    float iz0 = 1.f / (z0 + 1e-16f);
    float iz1 = 1.f / (z1 + 1e-16f);

    // --- pass 2: weighted feature accumulate (one LDG.128 per lane per edge) ---
    const uint4* T4 = (const uint4*)T;
    int hh = (lane >= SUBW / 2);
    float acc[16];
#pragma unroll
    for (int i = 0; i < 16; i++) acc[i] = 0.f;
    float wself = hh ? __expf(self1 - m1) * iz1 : __expf(self0 - m0) * iz0;
    acc16(T4, (size_t)w * SUBW + lane, wself, acc);
    for (int base = beg; base < end; base += SUBW) {
        int j = base + lane;
        int sj = w; float a0 = 0.f, a1 = 0.f;
        if (j < end) {
            sj = g_es[j];
            float2 eb = g_eb[j];
            a0 = __expf(eb.x - m0) * iz0;
            a1 = __expf(eb.y - m1) * iz1;
        }
        int cnt = min(SUBW, end - base);
        for (int t = 0; t < cnt; t++) {
            int s = __shfl_sync(gmask, sj, t, SUBW);
            float wa = __shfl_sync(gmask, a0, t, SUBW);
            float wb = __shfl_sync(gmask, a1, t, SUBW);
            float wgt = hh ? wb : wa;
            acc16(T4, (size_t)s * SUBW + lane, wgt, acc);
        }
    }

    if (CONCAT) {
#pragma unroll
        for (int k = 0; k < 4; k++) {
            float4 bb = ((const float4*)bias)[lane * 4 + k];
            float4 o;
            o.x = fmaxf(acc[4 * k + 0] + bb.x, 0.f);
            o.y = fmaxf(acc[4 * k + 1] + bb.y, 0.f);
            o.z = fmaxf(acc[4 * k + 2] + bb.z, 0.f);
            o.w = fmaxf(acc[4 * k + 3] + bb.w, 0.f);
            ((float4*)X)[(size_t)w * 32 + lane * 4 + k] = o;
        }
    } else {
        // SUBW=4: lanes 0,1 = head0 ch[lane*16..+15]; lanes 2,3 = head1 same ch.
        float v[16];
        int cl = lane & 1;
#pragma unroll
        for (int i = 0; i < 16; i++) {
            float oth = __shfl_sync(gmask, acc[i], (threadIdx.x & 2) ? (cl) : (cl + 2), 4);
            v[i] = 0.5f * (acc[i] + oth) + bias[cl * 16 + i];
        }
        float mx = v[0];
#pragma unroll
        for (int i = 1; i < 16; i++) mx = fmaxf(mx, v[i]);
        mx = fmaxf(mx, __shfl_xor_sync(gmask, mx, 1, 4));
        float sum = 0.f;
#pragma unroll
        for (int i = 0; i < 16; i++) sum += __expf(v[i] - mx);
        sum += __shfl_xor_sync(gmask, sum, 1, 4);
        float ls = logf(sum);
        if (lane < 2) {
#pragma unroll
            for (int k = 0; k < 4; k++) {
                float4 o;
                o.x = v[4 * k + 0] - mx - ls;
                o.y = v[4 * k + 1] - mx - ls;
                o.z = v[4 * k + 2] - mx - ls;
                o.w = v[4 * k + 3] - mx - ls;
                ((float4*)out)[(size_t)w * 8 + cl * 4 + k] = o;
            }
        }
    }
}

// ---------------- launcher ----------------
static inline int cdiv(long long a, int b) { return (int)((a + b - 1) / b); }

extern "C" void kernel_launch(void* const* d_in, const int* in_sizes, int n_in,
                              void* d_out, int out_size) {
    const float* x   = (const float*)d_in[0];
    const int*   ei  = (const int*)d_in[1];
    const float* W1  = (const float*)d_in[2];
    const float* b1  = (const float*)d_in[3];
    const float* W2  = (const float*)d_in[4];
    const float* b2  = (const float*)d_in[5];
    const float* Wg1 = (const float*)d_in[6];
    const float* as1 = (const float*)d_in[7];
    const float* ad1 = (const float*)d_in[8];
    const float* bg1 = (const float*)d_in[9];
    const float* Wg2 = (const float*)d_in[10];
    const float* as2 = (const float*)d_in[11];
    const float* ad2 = (const float*)d_in[12];
    const float* bg2 = (const float*)d_in[13];

    int n = in_sizes[0] / 128;
    int e = in_sizes[1] / 2;
    const int* src = ei;
    const int* dst = ei + e;

    unsigned char* T = nullptr; cudaGetSymbolAddress((void**)&T, g_bufT);
    float* X = nullptr; cudaGetSymbolAddress((void**)&X, g_bufX);
    float* out = (float*)d_out;

    static cudaStream_t s1 = nullptr;
    static cudaEvent_t e0 = nullptr, eCsr = nullptr;
    if (!s1) {
        cudaStreamCreateWithFlags(&s1, cudaStreamNonBlocking);
        cudaEventCreateWithFlags(&e0, cudaEventDisableTiming);
        cudaEventCreateWithFlags(&eCsr, cudaEventDisableTiming);
    }

    const int B = 256;
    int quad_blocks = cdiv((long long)n * 4, 160);    // 1250 exact (block=160)
    int oct_blocks  = cdiv((long long)n * 8, 128);    // 3125 exact (block=128)
    int gemm_blocks = cdiv(n, 128);

    // --- fork: CSR build on side stream (fully overlapped with GEMM1) ---
    cudaEventRecord(e0, 0);
    cudaStreamWaitEvent(s1, e0, 0);
    k_cnt_zero<<<cdiv(n, B), B, 0, s1>>>(n);
    k_hist<<<cdiv(e, B), B, 0, s1>>>(dst, e);
    k_off<<<cdiv(n, B), B, 0, s1>>>(n);
    k_fill<<<cdiv(e, B), B, 0, s1>>>(src, dst, e);
    cudaEventRecord(eCsr, s1);

    // --- GCN1: 128 -> 64 (no dinv dependency; per-edge dinv in node kernel) ---
    k_gemm<128, 64, 0, false><<<gemm_blocks, 256>>>(x, W1, T, nullptr, nullptr, n);
    cudaStreamWaitEvent(0, eCsr, 0);     // CSR + dinv ready before aggregation
    k_gcn_node<false><<<quad_blocks, 160>>>(T, b1, X, n);

    // --- GCN2: 64 -> 64 (rows pre-scaled by dinv; dinv already synced) ---
    k_gemm<64, 64, 0, true><<<gemm_blocks, 256>>>(X, W2, T, nullptr, nullptr, n);
    k_gcn_node<true><<<quad_blocks, 160>>>(T, b2, X, n);

    // --- GAT1: 64 -> 2x64 concat (scores fused into GEMM epilogue) ---
    k_gemm<64, 128, 1, false><<<gemm_blocks, 256>>>(X, Wg1, T, as1, ad1, n);
    k_gat_node<64, true><<<oct_blocks, 128>>>(T, bg1, X, nullptr, n);

    // --- GAT2: 128 -> 2x32 mean + log_softmax ---
    k_gemm<128, 64, 2, false><<<gemm_blocks, 256>>>(X, Wg2, T, as2, ad2, n);
    k_gat_node<32, false><<<quad_blocks, 160>>>(T, bg2, nullptr, out, n);
}

// round 13
// speedup vs baseline: 1.3662x; 1.0611x over previous
#include <cuda_runtime.h>
#include <cuda_fp16.h>
#include <cuda_fp8.h>

#define NN 50000
#define EE 800000
#define FULL 0xffffffffu

// ---------------- device scratch ----------------
__device__ __align__(16) unsigned char g_bufT[NN * 128]; // messages, fp8 e4m3 (bytes)
__device__ __align__(16) float g_bufX[NN * 128];         // layer activations (fp32)
__device__ float  g_dinv[NN];
__device__ int    g_cnt[NN];
__device__ int    g_off[NN];
__device__ int    g_cur[NN];
__device__ int    g_tot;
__device__ int    g_es[EE];          // CSR: src ids grouped by dst
__device__ float2 g_Sv[NN];          // per-node per-head <g, a_src>
__device__ float2 g_Dv[NN];          // per-node per-head <g, a_dst>
__device__ float2 g_eb[EE];          // cached per-edge raw scores (2 heads)

// ---------------- helpers ----------------
__device__ __forceinline__ float lrelu(float x) { return x > 0.f ? x : 0.2f * x; }

// packed f32x2 FMA: d = a*b + d (bit-exact 2x FFMA, Blackwell FFMA2)
__device__ __forceinline__ void ffma2(unsigned long long& d, unsigned long long a,
                                      unsigned long long b) {
    asm("fma.rn.f32x2 %0, %1, %2, %0;" : "+l"(d) : "l"(a), "l"(b));
}
__device__ __forceinline__ unsigned long long pack_dup(float x) {
    unsigned long long r;
    asm("mov.b64 %0, {%1, %1};" : "=l"(r) : "r"(__float_as_uint(x)));
    return r;
}
__device__ __forceinline__ void unpack2(unsigned long long v, float& lo, float& hi) {
    unsigned a, b;
    asm("mov.b64 {%0, %1}, %2;" : "=r"(a), "=r"(b) : "l"(v));
    lo = __uint_as_float(a);
    hi = __uint_as_float(b);
}

// fp8 gather with half2 HFMA2 accumulation: 1 LDG + 8 cvt + 8 HFMA2 per 16 channels
__device__ __forceinline__ void acc16h(const uint4* __restrict__ base, size_t idx,
                                       __half2 w, __half2* acc) {
    uint4 q = __ldg(base + idx);
    unsigned v[4] = {q.x, q.y, q.z, q.w};
#pragma unroll
    for (int k = 0; k < 4; k++) {
        __half2_raw h0 = __nv_cvt_fp8x2_to_halfraw2((__nv_fp8x2_storage_t)(v[k] & 0xFFFFu), __NV_E4M3);
        __half2_raw h1 = __nv_cvt_fp8x2_to_halfraw2((__nv_fp8x2_storage_t)(v[k] >> 16), __NV_E4M3);
        acc[2 * k + 0] = __hfma2(*(__half2*)&h0, w, acc[2 * k + 0]);
        acc[2 * k + 1] = __hfma2(*(__half2*)&h1, w, acc[2 * k + 1]);
    }
}
__device__ __forceinline__ void h2tof(const __half2* acc, float* f) {
#pragma unroll
    for (int k = 0; k < 8; k++) {
        float2 t = __half22float2(acc[k]);
        f[2 * k] = t.x;
        f[2 * k + 1] = t.y;
    }
}

__device__ __forceinline__ unsigned pack_fp8x4(float a, float b, float c, float d) {
    unsigned short p0 = __nv_cvt_float2_to_fp8x2(make_float2(a, b), __NV_SATFINITE, __NV_E4M3);
    unsigned short p1 = __nv_cvt_float2_to_fp8x2(make_float2(c, d), __NV_SATFINITE, __NV_E4M3);
    return (unsigned)p0 | ((unsigned)p1 << 16);
}

// ---------------- CSR build ----------------
__global__ void k_cnt_zero(int n) {
    int i = blockIdx.x * blockDim.x + threadIdx.x;
    if (i == 0) g_tot = 0;
    if (i < n) g_cnt[i] = 0;
}
__global__ void k_hist(const int* __restrict__ dst, int e) {
    int i = blockIdx.x * blockDim.x + threadIdx.x;
    if (i < e) atomicAdd(&g_cnt[dst[i]], 1);
}
__global__ void k_off(int n) {
    int i = blockIdx.x * blockDim.x + threadIdx.x;
    if (i >= n) return;
    int c = g_cnt[i];
    int p = atomicAdd(&g_tot, c);
    g_off[i] = p;
    g_cur[i] = p;
    g_dinv[i] = rsqrtf((float)(c + 1));
}
__global__ void k_fill(const int* __restrict__ src, const int* __restrict__ dst, int e) {
    int i = blockIdx.x * blockDim.x + threadIdx.x;
    if (i >= e) return;
    int d = dst[i];
    int p = atomicAdd(&g_cur[d], 1);
    g_es[p] = src[i];
}

// ---------------- register-tiled GEMM (FFMA2 inner loop): Y = X @ W, fp8 out -------
template <int K, int J, int SD, bool SCALE>
__global__ __launch_bounds__(256)
void k_gemm(const float* __restrict__ X, const float* __restrict__ W,
            unsigned char* __restrict__ Y, const float* __restrict__ asv,
            const float* __restrict__ adv, int n) {
    __shared__ float Ws[K * J];
    __shared__ float Xs[32 * 128];
    const int JT = J / 64;
    int tid = threadIdx.x;
    int tx = tid & 15, ty = tid >> 4;
    int row0 = blockIdx.x * 128;

    for (int i = tid; i < K * J / 4; i += 256)
        ((float4*)Ws)[i] = ((const float4*)W)[i];

    unsigned long long acc2[JT][8][2];
#pragma unroll
    for (int jc = 0; jc < JT; jc++)
#pragma unroll
        for (int i = 0; i < 8; i++) {
            acc2[jc][i][0] = 0ull;
            acc2[jc][i][1] = 0ull;
        }

    for (int k0 = 0; k0 < K; k0 += 32) {
        __syncthreads();
#pragma unroll
        for (int it = 0; it < 4; it++) {
            int i = tid + it * 256;
            int r = i >> 3, c4 = i & 7;
            int gr = row0 + r;
            float4 v = make_float4(0.f, 0.f, 0.f, 0.f);
            if (gr < n) v = ((const float4*)X)[(size_t)gr * (K / 4) + (k0 >> 2) + c4];
            int kk = c4 * 4;
            Xs[(kk + 0) * 128 + r] = v.x;
            Xs[(kk + 1) * 128 + r] = v.y;
            Xs[(kk + 2) * 128 + r] = v.z;
            Xs[(kk + 3) * 128 + r] = v.w;
        }
        __syncthreads();
#pragma unroll
        for (int kk = 0; kk < 32; kk++) {
            float xr[8];
            *(float4*)xr = *(const float4*)(Xs + kk * 128 + ty * 8);
            *(float4*)(xr + 4) = *(const float4*)(Xs + kk * 128 + ty * 8 + 4);
            unsigned long long xp[8];
#pragma unroll
            for (int i = 0; i < 8; i++) xp[i] = pack_dup(xr[i]);
#pragma unroll
            for (int jc = 0; jc < JT; jc++) {
                ulonglong2 w = *(const ulonglong2*)(Ws + (k0 + kk) * J + jc * 64 + tx * 4);
#pragma unroll
                for (int i = 0; i < 8; i++) {
                    ffma2(acc2[jc][i][0], xp[i], w.x);
                    ffma2(acc2[jc][i][1], xp[i], w.y);
                }
            }
        }
    }

    float acc[JT][8][4];
#pragma unroll
    for (int jc = 0; jc < JT; jc++)
#pragma unroll
        for (int i = 0; i < 8; i++) {
            unpack2(acc2[jc][i][0], acc[jc][i][0], acc[jc][i][1]);
            unpack2(acc2[jc][i][1], acc[jc][i][2], acc[jc][i][3]);
        }

#pragma unroll
    for (int i = 0; i < 8; i++) {
        int gr = row0 + ty * 8 + i;
        if (gr >= n) continue;
        float dd = SCALE ? g_dinv[gr] : 1.f;
#pragma unroll
        for (int jc = 0; jc < JT; jc++) {
            unsigned st = pack_fp8x4(dd * acc[jc][i][0], dd * acc[jc][i][1],
                                     dd * acc[jc][i][2], dd * acc[jc][i][3]);
            ((unsigned*)Y)[(size_t)gr * (J / 4) + jc * 16 + tx] = st;
        }
    }

    if (SD == 1) {
        float as[2][4], ad[2][4];
#pragma unroll
        for (int jc = 0; jc < JT; jc++)
#pragma unroll
            for (int c = 0; c < 4; c++) {
                as[jc][c] = asv[jc * 64 + tx * 4 + c];
                ad[jc][c] = adv[jc * 64 + tx * 4 + c];
            }
#pragma unroll
        for (int i = 0; i < 8; i++) {
            float s0 = 0.f, d0 = 0.f, s1 = 0.f, d1 = 0.f;
#pragma unroll
            for (int c = 0; c < 4; c++) {
                s0 += acc[0][i][c] * as[0][c];
                d0 += acc[0][i][c] * ad[0][c];
                s1 += acc[JT - 1][i][c] * as[1][c];
                d1 += acc[JT - 1][i][c] * ad[1][c];
            }
#pragma unroll
            for (int o = 8; o; o >>= 1) {
                s0 += __shfl_xor_sync(FULL, s0, o);
                d0 += __shfl_xor_sync(FULL, d0, o);
                s1 += __shfl_xor_sync(FULL, s1, o);
                d1 += __shfl_xor_sync(FULL, d1, o);
            }
            int gr = row0 + ty * 8 + i;
            if (tx == 0 && gr < n) {
                g_Sv[gr] = make_float2(s0, s1);
                g_Dv[gr] = make_float2(d0, d1);
            }
        }
    } else if (SD == 2) {
        float as[4], ad[4];
        int h = tx >> 3;
#pragma unroll
        for (int c = 0; c < 4; c++) {
            as[c] = asv[h * 32 + (tx & 7) * 4 + c];
            ad[c] = adv[h * 32 + (tx & 7) * 4 + c];
        }
#pragma unroll
        for (int i = 0; i < 8; i++) {
            float s = 0.f, d = 0.f;
#pragma unroll
            for (int c = 0; c < 4; c++) {
                s += acc[0][i][c] * as[c];
                d += acc[0][i][c] * ad[c];
            }
#pragma unroll
            for (int o = 4; o; o >>= 1) {
                s += __shfl_xor_sync(FULL, s, o);
                d += __shfl_xor_sync(FULL, d, o);
            }
            int gr = row0 + ty * 8 + i;
            if ((tx & 7) == 0 && gr < n) {
                ((float*)g_Sv)[gr * 2 + h] = s;
                ((float*)g_Dv)[gr * 2 + h] = d;
            }
        }
    }
}

// ---------------- GCN: 4 lanes/node, fp8 rows, half2 accumulation ------------------
template <bool PRESCALED>
__global__ __launch_bounds__(160)
void k_gcn_node(const unsigned char* __restrict__ T, const float* __restrict__ b,
                float* __restrict__ X, int n) {
    int g = blockIdx.x * blockDim.x + threadIdx.x;
    int w = g >> 2;
    int lane = threadIdx.x & 3;
    unsigned gmask = 0xFu << ((threadIdx.x & 31) & ~3);
    if (w >= n) return;   // subgroup exits together; mask stays valid
    const uint4* T4 = (const uint4*)T;   // row = 64 fp8 = 4 uint4
    float dw = g_dinv[w];
    const __half2 ONE2 = __float2half2_rn(1.f);
    __half2 acch[8];
#pragma unroll
    for (int i = 0; i < 8; i++) acch[i] = __float2half2_rn(0.f);
    acc16h(T4, (size_t)w * 4 + lane, PRESCALED ? ONE2 : __float2half2_rn(dw), acch);
    int beg = g_off[w], end = beg + g_cnt[w];
    for (int base = beg; base < end; base += 4) {
        int j = base + lane;
        int sj = w; float cj = 0.f;
        if (j < end) { sj = g_es[j]; cj = PRESCALED ? 1.f : g_dinv[sj]; }
        int cnt = min(4, end - base);
        for (int t = 0; t < cnt; t++) {
            int s = __shfl_sync(gmask, sj, t, 4);
            __half2 c2 = ONE2;
            if (!PRESCALED) {
                float c = __shfl_sync(gmask, cj, t, 4);
                c2 = __float2half2_rn(c);
            }
            acc16h(T4, (size_t)s * 4 + lane, c2, acch);
        }
    }
    float acc[16];
    h2tof(acch, acc);
#pragma unroll
    for (int k = 0; k < 4; k++) {
        float4 bb = ((const float4*)b)[lane * 4 + k];
        float4 o;
        o.x = fmaxf(dw * acc[4 * k + 0] + bb.x, 0.f);
        o.y = fmaxf(dw * acc[4 * k + 1] + bb.y, 0.f);
        o.z = fmaxf(dw * acc[4 * k + 2] + bb.z, 0.f);
        o.w = fmaxf(dw * acc[4 * k + 3] + bb.w, 0.f);
        ((float4*)X)[(size_t)w * 16 + lane * 4 + k] = o;
    }
}

// ---------------- fused GAT layer: SUBW lanes/node, fp8 rows, half2 accumulation ---
template <int CH, bool CONCAT>
__global__ void k_gat_node(const unsigned char* __restrict__ T,
                           const float* __restrict__ bias,
                           float* __restrict__ X, float* __restrict__ out, int n) {
    constexpr int SUBW = (CH == 64) ? 8 : 4;   // row = 2*CH fp8 = SUBW uint4
    int g = blockIdx.x * blockDim.x + threadIdx.x;
    int w = g / SUBW;
    int lane = threadIdx.x & (SUBW - 1);
    unsigned gmask = (SUBW == 8) ? (0xFFu << ((threadIdx.x & 31) & ~7))
                                 : (0xFu << ((threadIdx.x & 31) & ~3));
    if (w >= n) return;   // subgroup exits together
    float2 Dd = g_Dv[w];
    float2 Sw = g_Sv[w];
    float self0 = lrelu(Sw.x + Dd.x);
    float self1 = lrelu(Sw.y + Dd.y);
    int beg = g_off[w], end = beg + g_cnt[w];

    // --- pass 1: online max+sum over incoming scores, cache raw scores ---
    float m0 = (lane == 0) ? self0 : -1e30f;
    float m1 = (lane == 0) ? self1 : -1e30f;
    float z0 = (lane == 0) ? 1.f : 0.f;
    float z1 = (lane == 0) ? 1.f : 0.f;
    for (int j = beg + lane; j < end; j += SUBW) {
        float2 sv = g_Sv[g_es[j]];
        float e0 = lrelu(sv.x + Dd.x);
        float e1 = lrelu(sv.y + Dd.y);
        g_eb[j] = make_float2(e0, e1);
        if (e0 > m0) { z0 = z0 * __expf(m0 - e0) + 1.f; m0 = e0; }
        else           z0 += __expf(e0 - m0);
        if (e1 > m1) { z1 = z1 * __expf(m1 - e1) + 1.f; m1 = e1; }
        else           z1 += __expf(e1 - m1);
    }
#pragma unroll
    for (int o = SUBW / 2; o; o >>= 1) {
        float om = __shfl_xor_sync(gmask, m0, o, SUBW);
        float oz = __shfl_xor_sync(gmask, z0, o, SUBW);
        float M = fmaxf(m0, om);
        z0 = z0 * __expf(m0 - M) + oz * __expf(om - M);
        m0 = M;
        om = __shfl_xor_sync(gmask, m1, o, SUBW);
        oz = __shfl_xor_sync(gmask, z1, o, SUBW);
        M = fmaxf(m1, om);
        z1 = z1 * __expf(m1 - M) + oz * __expf(om - M);
        m1 = M;
    }
    float iz0 = 1.f / (z0 + 1e-16f);
    float iz1 = 1.f / (z1 + 1e-16f);

    // --- pass 2: weighted feature accumulate (half2 HFMA2) ---
    const uint4* T4 = (const uint4*)T;
    int hh = (lane >= SUBW / 2);
    __half2 acch[8];
#pragma unroll
    for (int i = 0; i < 8; i++) acch[i] = __float2half2_rn(0.f);
    float wself = hh ? __expf(self1 - m1) * iz1 : __expf(self0 - m0) * iz0;
    acc16h(T4, (size_t)w * SUBW + lane, __float2half2_rn(wself), acch);
    for (int base = beg; base < end; base += SUBW) {
        int j = base + lane;
        int sj = w; float a0 = 0.f, a1 = 0.f;
        if (j < end) {
            sj = g_es[j];
            float2 eb = g_eb[j];
            a0 = __expf(eb.x - m0) * iz0;
            a1 = __expf(eb.y - m1) * iz1;
        }
        int cnt = min(SUBW, end - base);
        for (int t = 0; t < cnt; t++) {
            int s = __shfl_sync(gmask, sj, t, SUBW);
            float wa = __shfl_sync(gmask, a0, t, SUBW);
            float wb = __shfl_sync(gmask, a1, t, SUBW);
            float wgt = hh ? wb : wa;
            acc16h(T4, (size_t)s * SUBW + lane, __float2half2_rn(wgt), acch);
        }
    }
    float acc[16];
    h2tof(acch, acc);

    if (CONCAT) {
#pragma unroll
        for (int k = 0; k < 4; k++) {
            float4 bb = ((const float4*)bias)[lane * 4 + k];
            float4 o;
            o.x = fmaxf(acc[4 * k + 0] + bb.x, 0.f);
            o.y = fmaxf(acc[4 * k + 1] + bb.y, 0.f);
            o.z = fmaxf(acc[4 * k + 2] + bb.z, 0.f);
            o.w = fmaxf(acc[4 * k + 3] + bb.w, 0.f);
            ((float4*)X)[(size_t)w * 32 + lane * 4 + k] = o;
        }
    } else {
        // SUBW=4: lanes 0,1 = head0 ch[lane*16..+15]; lanes 2,3 = head1 same ch.
        float v[16];
        int cl = lane & 1;
#pragma unroll
        for (int i = 0; i < 16; i++) {
            float oth = __shfl_sync(gmask, acc[i], (threadIdx.x & 2) ? (cl) : (cl + 2), 4);
            v[i] = 0.5f * (acc[i] + oth) + bias[cl * 16 + i];
        }
        float mx = v[0];
#pragma unroll
        for (int i = 1; i < 16; i++) mx = fmaxf(mx, v[i]);
        mx = fmaxf(mx, __shfl_xor_sync(gmask, mx, 1, 4));
        float sum = 0.f;
#pragma unroll
        for (int i = 0; i < 16; i++) sum += __expf(v[i] - mx);
        sum += __shfl_xor_sync(gmask, sum, 1, 4);
        float ls = logf(sum);
        if (lane < 2) {
#pragma unroll
            for (int k = 0; k < 4; k++) {
                float4 o;
                o.x = v[4 * k + 0] - mx - ls;
                o.y = v[4 * k + 1] - mx - ls;
                o.z = v[4 * k + 2] - mx - ls;
                o.w = v[4 * k + 3] - mx - ls;
                ((float4*)out)[(size_t)w * 8 + cl * 4 + k] = o;
            }
        }
    }
}

// ---------------- launcher ----------------
static inline int cdiv(long long a, int b) { return (int)((a + b - 1) / b); }

extern "C" void kernel_launch(void* const* d_in, const int* in_sizes, int n_in,
                              void* d_out, int out_size) {
    const float* x   = (const float*)d_in[0];
    const int*   ei  = (const int*)d_in[1];
    const float* W1  = (const float*)d_in[2];
    const float* b1  = (const float*)d_in[3];
    const float* W2  = (const float*)d_in[4];
    const float* b2  = (const float*)d_in[5];
    const float* Wg1 = (const float*)d_in[6];
    const float* as1 = (const float*)d_in[7];
    const float* ad1 = (const float*)d_in[8];
    const float* bg1 = (const float*)d_in[9];
    const float* Wg2 = (const float*)d_in[10];
    const float* as2 = (const float*)d_in[11];
    const float* ad2 = (const float*)d_in[12];
    const float* bg2 = (const float*)d_in[13];

    int n = in_sizes[0] / 128;
    int e = in_sizes[1] / 2;
    const int* src = ei;
    const int* dst = ei + e;

    unsigned char* T = nullptr; cudaGetSymbolAddress((void**)&T, g_bufT);
    float* X = nullptr; cudaGetSymbolAddress((void**)&X, g_bufX);
    float* out = (float*)d_out;

    static cudaStream_t s1 = nullptr;
    static cudaEvent_t e0 = nullptr, eCsr = nullptr;
    if (!s1) {
        cudaStreamCreateWithFlags(&s1, cudaStreamNonBlocking);
        cudaEventCreateWithFlags(&e0, cudaEventDisableTiming);
        cudaEventCreateWithFlags(&eCsr, cudaEventDisableTiming);
    }

    const int B = 256;
    int quad_blocks = cdiv((long long)n * 4, 160);    // 1250 exact (block=160)
    int oct_blocks  = cdiv((long long)n * 8, 128);    // 3125 exact (block=128)
    int gemm_blocks = cdiv(n, 128);

    // --- fork: CSR build on side stream (fully overlapped with GEMM1) ---
    cudaEventRecord(e0, 0);
    cudaStreamWaitEvent(s1, e0, 0);
    k_cnt_zero<<<cdiv(n, B), B, 0, s1>>>(n);
    k_hist<<<cdiv(e, B), B, 0, s1>>>(dst, e);
    k_off<<<cdiv(n, B), B, 0, s1>>>(n);
    k_fill<<<cdiv(e, B), B, 0, s1>>>(src, dst, e);
    cudaEventRecord(eCsr, s1);

    // --- GCN1: 128 -> 64 (no dinv dependency; per-edge dinv in node kernel) ---
    k_gemm<128, 64, 0, false><<<gemm_blocks, 256>>>(x, W1, T, nullptr, nullptr, n);
    cudaStreamWaitEvent(0, eCsr, 0);     // CSR + dinv ready before aggregation
    k_gcn_node<false><<<quad_blocks, 160>>>(T, b1, X, n);

    // --- GCN2: 64 -> 64 (rows pre-scaled by dinv; dinv already synced) ---
    k_gemm<64, 64, 0, true><<<gemm_blocks, 256>>>(X, W2, T, nullptr, nullptr, n);
    k_gcn_node<true><<<quad_blocks, 160>>>(T, b2, X, n);

    // --- GAT1: 64 -> 2x64 concat (scores fused into GEMM epilogue) ---
    k_gemm<64, 128, 1, false><<<gemm_blocks, 256>>>(X, Wg1, T, as1, ad1, n);
    k_gat_node<64, true><<<oct_blocks, 128>>>(T, bg1, X, nullptr, n);

    // --- GAT2: 128 -> 2x32 mean + log_softmax ---
    k_gemm<128, 64, 2, false><<<gemm_blocks, 256>>>(X, Wg2, T, as2, ad2, n);
    k_gat_node<32, false><<<quad_blocks, 160>>>(T, bg2, nullptr, out, n);
}